// round 2
// baseline (speedup 1.0000x reference)
#include <cuda_runtime.h>
#include <cuda_bf16.h>
#include <math.h>

#define HIDDEN 256
#define HS     512
#define NHEADS 8
#define HDIM   64
#define NTOK   8
#define BATCH  8
#define HH     32
#define WW     32
#define PIXB   (HH*WW)        // 1024 pixels per batch
#define NPIX   (BATCH*PIXB)   // 8192
#define EPSV   1e-6f
#define ATTN_SCALE 0.125f     // 64^-0.5

// ---------------- device scratch (static, no allocation) ----------------
__device__ float g_qh[BATCH*HS];                    // [b][512]
__device__ float g_wqc[BATCH*NHEADS*HIDDEN];        // [b][e][256]  (scale & rms_w folded)
__device__ float g_cbar[NHEADS*HIDDEN*NPIX];        // [e][ch][pix]
__device__ float g_h[HS*NPIX];                      // [e*64+d][pix]

// ---------------- K0: query MLP -> qh[b][512] ----------------
__global__ __launch_bounds__(512) void k_qh(
    const int* __restrict__ q, const float* __restrict__ emb,
    const float* __restrict__ w1, const float* __restrict__ b1,
    const float* __restrict__ w2, const float* __restrict__ b2)
{
    __shared__ float qe[HIDDEN];
    __shared__ float t[HS];
    int b = blockIdx.x;
    int tid = threadIdx.x;
    if (tid < HIDDEN) qe[tid] = emb[q[b]*HIDDEN + tid];
    __syncthreads();
    // t = silu(qe @ w1 + b1)
    float acc = b1[tid];
    #pragma unroll 8
    for (int ch = 0; ch < HIDDEN; ch++) acc = fmaf(qe[ch], w1[ch*HS + tid], acc);
    t[tid] = acc / (1.f + expf(-acc));
    __syncthreads();
    float acc2 = b2[tid];
    #pragma unroll 8
    for (int k = 0; k < HS; k++) acc2 = fmaf(t[k], w2[k*HS + tid], acc2);
    g_qh[b*HS + tid] = acc2;
}

// ---------------- K1: wqc[b][e][ch] = scale*rms_w[ch]* sum_d qh[b][e*64+d]*w_kv[ch][e*128+d]
// NOTE: kv reshape groups 1024 cols as [head][2*64]; K = cols [e*128, e*128+64)
__global__ __launch_bounds__(256) void k_wqc(
    const float* __restrict__ w_kv, const float* __restrict__ rms_w)
{
    int e = blockIdx.x, b = blockIdx.y;
    int ch = threadIdx.x;
    __shared__ float qh_s[HDIM];
    if (ch < HDIM) qh_s[ch] = g_qh[b*HS + e*HDIM + ch];
    __syncthreads();
    const float4* wk = (const float4*)(w_kv + ch*(2*HS) + e*(2*HDIM));
    float acc = 0.f;
    #pragma unroll
    for (int d4 = 0; d4 < HDIM/4; d4++) {
        float4 w = wk[d4];
        acc = fmaf(qh_s[d4*4+0], w.x, acc);
        acc = fmaf(qh_s[d4*4+1], w.y, acc);
        acc = fmaf(qh_s[d4*4+2], w.z, acc);
        acc = fmaf(qh_s[d4*4+3], w.w, acc);
    }
    g_wqc[(b*NHEADS + e)*HIDDEN + ch] = acc * rms_w[ch] * ATTN_SCALE;
}

// ---------------- K2: per (b,h) row: rmsnorm-dots + softmax -> cbar ----------------
// Block = one (b,h) row of 32 pixels, 256 threads (8 warps). Warp w handles token n=w in pass A.
__global__ __launch_bounds__(256) void k_attn(const float* __restrict__ c)
{
    __shared__ float swq[NHEADS*HIDDEN];          // wqc for this batch
    __shared__ float s_s[NHEADS*NTOK*32];         // [e][n][p]
    __shared__ float rms_s[NTOK*32];              // [n][p]
    __shared__ float a_s[NHEADS*NTOK*32];         // [e][n][p] = attn*inv_rms

    int b = blockIdx.x >> 5;
    int h = blockIdx.x & 31;
    int tid = threadIdx.x;
    int warp = tid >> 5, lane = tid & 31;

    for (int i = tid; i < NHEADS*HIDDEN; i += 256) swq[i] = g_wqc[b*NHEADS*HIDDEN + i];
    __syncthreads();

    // ---- pass A: sumsq + dots (warp = token n, lane = pixel p) ----
    {
        const float* cp = c + ((size_t)(b*NTOK + warp)*HIDDEN)*PIXB + h*WW + lane;
        float ss = 0.f;
        float sd[NHEADS];
        #pragma unroll
        for (int e = 0; e < NHEADS; e++) sd[e] = 0.f;
        #pragma unroll 4
        for (int ch = 0; ch < HIDDEN; ch++) {
            float v = cp[(size_t)ch*PIXB];
            ss = fmaf(v, v, ss);
            #pragma unroll
            for (int e = 0; e < NHEADS; e++) sd[e] = fmaf(v, swq[e*HIDDEN + ch], sd[e]);
        }
        rms_s[warp*32 + lane] = rsqrtf(ss*(1.0f/HIDDEN) + EPSV);
        #pragma unroll
        for (int e = 0; e < NHEADS; e++) s_s[(e*NTOK + warp)*32 + lane] = sd[e];
    }
    __syncthreads();

    // ---- softmax: thread = (e = tid>>5, p = tid&31) ----
    {
        int e = tid >> 5, p = tid & 31;
        float d[NTOK], m = -1e30f;
        #pragma unroll
        for (int n = 0; n < NTOK; n++) {
            d[n] = s_s[(e*NTOK + n)*32 + p] * rms_s[n*32 + p];
            m = fmaxf(m, d[n]);
        }
        float sum = 0.f;
        #pragma unroll
        for (int n = 0; n < NTOK; n++) { d[n] = expf(d[n] - m); sum += d[n]; }
        float inv = 1.f / sum;
        #pragma unroll
        for (int n = 0; n < NTOK; n++)
            a_s[(e*NTOK + n)*32 + p] = d[n] * inv * rms_s[n*32 + p];
    }
    __syncthreads();

    // ---- pass B: cbar[e][ch][pix] = sum_n a[e][n]*c[n][ch]  (warp = ch chunk, lane = pixel) ----
    float ar[NHEADS][NTOK];
    #pragma unroll
    for (int e = 0; e < NHEADS; e++)
        #pragma unroll
        for (int n = 0; n < NTOK; n++) ar[e][n] = a_s[(e*NTOK + n)*32 + lane];

    int pix = b*PIXB + h*WW + lane;
    for (int cc = 0; cc < 32; cc++) {
        int ch = warp*32 + cc;
        const float* cpp = c + ((size_t)(b*NTOK)*HIDDEN + ch)*PIXB + h*WW + lane;
        float cb[NHEADS];
        #pragma unroll
        for (int e = 0; e < NHEADS; e++) cb[e] = 0.f;
        #pragma unroll
        for (int n = 0; n < NTOK; n++) {
            float v = cpp[(size_t)n*HIDDEN*PIXB];
            #pragma unroll
            for (int e = 0; e < NHEADS; e++) cb[e] = fmaf(ar[e][n], v, cb[e]);
        }
        #pragma unroll
        for (int e = 0; e < NHEADS; e++)
            g_cbar[((size_t)e*HIDDEN + ch)*NPIX + pix] = cb[e];
    }
}

// ---------------- K3: GEMM1 per head: H_e[64, 8192] = Wv_e^T[64,256] @ Cbar_e[256,8192]
// V weights: w_kv cols [e*128+64, e*128+128), rms_w folded. Block tile 64x256, thread 8x8.
__global__ __launch_bounds__(256) void k_gemm1(
    const float* __restrict__ w_kv, const float* __restrict__ rms_w)
{
    __shared__ float sA[32*64];    // [k][d]
    __shared__ float sB[32*256];   // [k][p]
    int e   = blockIdx.y;
    int px0 = blockIdx.x * 256;
    int lane = threadIdx.x & 31, warp = threadIdx.x >> 5;

    float acc[8][8];
    #pragma unroll
    for (int i = 0; i < 8; i++)
        #pragma unroll
        for (int j = 0; j < 8; j++) acc[i][j] = 0.f;

    for (int kc = 0; kc < HIDDEN; kc += 32) {
        #pragma unroll
        for (int i = 0; i < 8; i++) {
            int idx = threadIdx.x + i*256;
            int k = idx >> 6, d = idx & 63;
            sA[idx] = rms_w[kc + k] * w_kv[(size_t)(kc + k)*(2*HS) + e*(2*HDIM) + HDIM + d];
        }
        #pragma unroll
        for (int i = 0; i < 8; i++) {
            int f4 = threadIdx.x + i*256;
            int k = f4 >> 6, p4 = f4 & 63;
            ((float4*)sB)[f4] =
                *(const float4*)&g_cbar[((size_t)e*HIDDEN + kc + k)*NPIX + px0 + p4*4];
        }
        __syncthreads();
        #pragma unroll
        for (int k = 0; k < 32; k++) {
            float aa[8], bb[8];
            *(float4*)(aa)   = *(const float4*)&sA[k*64 + warp*8];
            *(float4*)(aa+4) = *(const float4*)&sA[k*64 + warp*8 + 4];
            *(float4*)(bb)   = *(const float4*)&sB[k*256 + lane*8];
            *(float4*)(bb+4) = *(const float4*)&sB[k*256 + lane*8 + 4];
            #pragma unroll
            for (int i = 0; i < 8; i++)
                #pragma unroll
                for (int j = 0; j < 8; j++) acc[i][j] = fmaf(aa[i], bb[j], acc[i][j]);
        }
        __syncthreads();
    }
    int drow = e*HDIM + warp*8;
    #pragma unroll
    for (int i = 0; i < 8; i++) {
        float* dst = &g_h[(size_t)(drow + i)*NPIX + px0 + lane*8];
        *(float4*)(dst)   = make_float4(acc[i][0], acc[i][1], acc[i][2], acc[i][3]);
        *(float4*)(dst+4) = make_float4(acc[i][4], acc[i][5], acc[i][6], acc[i][7]);
    }
}

// ---------------- K4: GEMM2: out[256,8192] = W_out^T[256,512] @ H[512,8192] + b_out
// Block tile 64co x 256pix, thread 8x8; writes transposed output [b][co][h][w].
__global__ __launch_bounds__(256) void k_gemm2(
    const float* __restrict__ w_out, const float* __restrict__ b_out,
    float* __restrict__ out)
{
    __shared__ float sA[32*64];    // [k][co]
    __shared__ float sB[32*256];   // [k][p]
    int co0 = blockIdx.y * 64;
    int px0 = blockIdx.x * 256;
    int lane = threadIdx.x & 31, warp = threadIdx.x >> 5;

    float acc[8][8];
    #pragma unroll
    for (int i = 0; i < 8; i++)
        #pragma unroll
        for (int j = 0; j < 8; j++) acc[i][j] = 0.f;

    for (int kc = 0; kc < HS; kc += 32) {
        #pragma unroll
        for (int i = 0; i < 8; i++) {
            int idx = threadIdx.x + i*256;
            int k = idx >> 6, co = idx & 63;
            sA[idx] = w_out[(size_t)(kc + k)*HIDDEN + co0 + co];
        }
        #pragma unroll
        for (int i = 0; i < 8; i++) {
            int f4 = threadIdx.x + i*256;
            int k = f4 >> 6, p4 = f4 & 63;
            ((float4*)sB)[f4] = *(const float4*)&g_h[(size_t)(kc + k)*NPIX + px0 + p4*4];
        }
        __syncthreads();
        #pragma unroll
        for (int k = 0; k < 32; k++) {
            float aa[8], bb[8];
            *(float4*)(aa)   = *(const float4*)&sA[k*64 + warp*8];
            *(float4*)(aa+4) = *(const float4*)&sA[k*64 + warp*8 + 4];
            *(float4*)(bb)   = *(const float4*)&sB[k*256 + lane*8];
            *(float4*)(bb+4) = *(const float4*)&sB[k*256 + lane*8 + 4];
            #pragma unroll
            for (int i = 0; i < 8; i++)
                #pragma unroll
                for (int j = 0; j < 8; j++) acc[i][j] = fmaf(aa[i], bb[j], acc[i][j]);
        }
        __syncthreads();
    }
    int bb_ = px0 >> 10;           // batch of this pixel tile (256 | 1024)
    int hw  = px0 & 1023;
    #pragma unroll
    for (int i = 0; i < 8; i++) {
        int co = co0 + warp*8 + i;
        float bias = b_out[co];
        float* dst = out + ((size_t)(bb_*HIDDEN + co))*PIXB + hw + lane*8;
        *(float4*)(dst)   = make_float4(acc[i][0]+bias, acc[i][1]+bias, acc[i][2]+bias, acc[i][3]+bias);
        *(float4*)(dst+4) = make_float4(acc[i][4]+bias, acc[i][5]+bias, acc[i][6]+bias, acc[i][7]+bias);
    }
}

// ---------------- launch ----------------
extern "C" void kernel_launch(void* const* d_in, const int* in_sizes, int n_in,
                              void* d_out, int out_size)
{
    const int*   q     = (const int*)  d_in[0];
    const float* c     = (const float*)d_in[1];
    const float* rms_w = (const float*)d_in[2];
    const float* emb   = (const float*)d_in[3];
    const float* w1    = (const float*)d_in[4];
    const float* b1    = (const float*)d_in[5];
    const float* w2    = (const float*)d_in[6];
    const float* b2    = (const float*)d_in[7];
    const float* w_kv  = (const float*)d_in[8];
    const float* w_out = (const float*)d_in[9];
    const float* b_out = (const float*)d_in[10];
    float* out = (float*)d_out;

    k_qh  <<<BATCH, 512>>>(q, emb, w1, b1, w2, b2);
    k_wqc <<<dim3(NHEADS, BATCH), 256>>>(w_kv, rms_w);
    k_attn<<<BATCH*HH, 256>>>(c);
    k_gemm1<<<dim3(NPIX/256, NHEADS), 256>>>(w_kv, rms_w);
    k_gemm2<<<dim3(NPIX/256, HIDDEN/64), 256>>>(w_out, b_out, out);
}

// round 3
// speedup vs baseline: 1.1675x; 1.1675x over previous
#include <cuda_runtime.h>
#include <cuda_bf16.h>
#include <math.h>

#define HIDDEN 256
#define HS     512
#define NHEADS 8
#define HDIM   64
#define NTOK   8
#define BATCH  8
#define HH     32
#define WW     32
#define PIXB   (HH*WW)        // 1024 pixels per batch
#define NPIX   (BATCH*PIXB)   // 8192
#define EPSV   1e-6f
#define ATTN_SCALE 0.125f     // 64^-0.5

// ---------------- device scratch (static, no allocation) ----------------
__device__ float g_qh[BATCH*HS];                 // [b][512]
__device__ float g_wqc[BATCH*NHEADS*HIDDEN];     // [b][e][256]  (scale & rms_w folded)
__device__ float g_wv[NHEADS*HIDDEN*HDIM];       // [e][ch][d]   (rms_w folded V weights)
__device__ float g_h[HS*NPIX];                   // [e*64+d][pix]

// ---------------- K0: query MLP -> qh[b][512] ----------------
__global__ __launch_bounds__(512) void k_qh(
    const int* __restrict__ q, const float* __restrict__ emb,
    const float* __restrict__ w1, const float* __restrict__ b1,
    const float* __restrict__ w2, const float* __restrict__ b2)
{
    __shared__ float qe[HIDDEN];
    __shared__ float t[HS];
    int b = blockIdx.x;
    int tid = threadIdx.x;
    if (tid < HIDDEN) qe[tid] = emb[q[b]*HIDDEN + tid];
    __syncthreads();
    float acc = b1[tid];
    #pragma unroll 8
    for (int ch = 0; ch < HIDDEN; ch++) acc = fmaf(qe[ch], w1[ch*HS + tid], acc);
    t[tid] = acc / (1.f + expf(-acc));
    __syncthreads();
    float acc2 = b2[tid];
    #pragma unroll 8
    for (int k = 0; k < HS; k++) acc2 = fmaf(t[k], w2[k*HS + tid], acc2);
    g_qh[b*HS + tid] = acc2;
}

// ---------------- K1: wqc[b][e][ch] (K weights folded with qh, rms_w, scale) ----------------
__global__ __launch_bounds__(256) void k_wqc(
    const float* __restrict__ w_kv, const float* __restrict__ rms_w)
{
    int e = blockIdx.x, b = blockIdx.y;
    int ch = threadIdx.x;
    __shared__ float qh_s[HDIM];
    if (ch < HDIM) qh_s[ch] = g_qh[b*HS + e*HDIM + ch];
    __syncthreads();
    const float4* wk = (const float4*)(w_kv + ch*(2*HS) + e*(2*HDIM));
    float acc = 0.f;
    #pragma unroll
    for (int d4 = 0; d4 < HDIM/4; d4++) {
        float4 w = wk[d4];
        acc = fmaf(qh_s[d4*4+0], w.x, acc);
        acc = fmaf(qh_s[d4*4+1], w.y, acc);
        acc = fmaf(qh_s[d4*4+2], w.z, acc);
        acc = fmaf(qh_s[d4*4+3], w.w, acc);
    }
    g_wqc[(b*NHEADS + e)*HIDDEN + ch] = acc * rms_w[ch] * ATTN_SCALE;
}

// ---------------- K1b: repack V weights head-major with rms_w folded ----------------
// g_wv[e][ch][d] = rms_w[ch] * w_kv[ch][e*128 + 64 + d]
__global__ __launch_bounds__(512) void k_prep(
    const float* __restrict__ w_kv, const float* __restrict__ rms_w)
{
    int ch = blockIdx.x;
    int tid = threadIdx.x;
    int e = tid >> 6, d = tid & 63;
    g_wv[((size_t)e*HIDDEN + ch)*HDIM + d] =
        rms_w[ch] * w_kv[(size_t)ch*(2*HS) + e*(2*HDIM) + HDIM + d];
}

// ---------------- K2: fused rmsnorm + dots + softmax + cbar + V-GEMM -> g_h ----------------
// Block = one (b,h) row of 32 pixels, 256 threads (8 warps).
// Dynamic smem layout (floats):
//   swq  [0,2048)      wqc for this batch
//   s_s  [2048,4096)   dots [e][n][p]
//   rms  [4096,4352)   inv-rms [n][p]
//   a_s  [4352,6400)   attn*inv_rms [e][n][p]
//   cb_s [6400,22784)  cbar chunk [8e][64ch][32p]
__global__ __launch_bounds__(256, 2) void k_attn2(const float* __restrict__ c)
{
    extern __shared__ float sm[];
    float* swq   = sm;
    float* s_s   = sm + 2048;
    float* rms_s = sm + 4096;
    float* a_s   = sm + 4352;
    float* cb_s  = sm + 6400;

    int b = blockIdx.x >> 5;
    int h = blockIdx.x & 31;
    int tid = threadIdx.x;
    int warp = tid >> 5, lane = tid & 31;

    for (int i = tid; i < NHEADS*HIDDEN; i += 256) swq[i] = g_wqc[b*NHEADS*HIDDEN + i];
    __syncthreads();

    // ---- pass A: sumsq + dots (warp = token n, lane = pixel p) ----
    {
        const float* cp = c + ((size_t)(b*NTOK + warp)*HIDDEN)*PIXB + h*WW + lane;
        float ss = 0.f;
        float sd[NHEADS];
        #pragma unroll
        for (int e = 0; e < NHEADS; e++) sd[e] = 0.f;
        #pragma unroll 4
        for (int ch = 0; ch < HIDDEN; ch++) {
            float v = cp[(size_t)ch*PIXB];
            ss = fmaf(v, v, ss);
            #pragma unroll
            for (int e = 0; e < NHEADS; e++) sd[e] = fmaf(v, swq[e*HIDDEN + ch], sd[e]);
        }
        rms_s[warp*32 + lane] = rsqrtf(ss*(1.0f/HIDDEN) + EPSV);
        #pragma unroll
        for (int e = 0; e < NHEADS; e++) s_s[(e*NTOK + warp)*32 + lane] = sd[e];
    }
    __syncthreads();

    // ---- softmax: thread = (e = tid>>5, p = tid&31) ----
    {
        int e = tid >> 5, p = tid & 31;
        float d[NTOK], m = -1e30f;
        #pragma unroll
        for (int n = 0; n < NTOK; n++) {
            d[n] = s_s[(e*NTOK + n)*32 + p] * rms_s[n*32 + p];
            m = fmaxf(m, d[n]);
        }
        float sum = 0.f;
        #pragma unroll
        for (int n = 0; n < NTOK; n++) { d[n] = expf(d[n] - m); sum += d[n]; }
        float inv = 1.f / sum;
        #pragma unroll
        for (int n = 0; n < NTOK; n++)
            a_s[(e*NTOK + n)*32 + p] = d[n] * inv * rms_s[n*32 + p];
    }
    __syncthreads();

    // ---- chunked cbar + per-head V-GEMM ----
    // GEMM thread layout: warp = head e, lane = (dg = lane>>2, pg = lane&3)
    // acc[i][j] : d = dg*8+i, p = pg*8+j
    int dg = lane >> 2, pg = lane & 3;
    float acc[8][8];
    #pragma unroll
    for (int i = 0; i < 8; i++)
        #pragma unroll
        for (int j = 0; j < 8; j++) acc[i][j] = 0.f;

    for (int cbk = 0; cbk < 4; cbk++) {
        // phase B: cbar chunk, warp covers 8 channels (all 8 heads at once)
        #pragma unroll
        for (int cc = 0; cc < 8; cc++) {
            int chl = warp*8 + cc;              // local ch in [0,64)
            int ch  = cbk*64 + chl;
            const float* cp = c + ((size_t)(b*NTOK)*HIDDEN + ch)*PIXB + h*WW + lane;
            float v[NTOK];
            #pragma unroll
            for (int n = 0; n < NTOK; n++) v[n] = cp[(size_t)n*HIDDEN*PIXB];
            #pragma unroll
            for (int e = 0; e < NHEADS; e++) {
                float s = 0.f;
                #pragma unroll
                for (int n = 0; n < NTOK; n++)
                    s = fmaf(a_s[(e*NTOK + n)*32 + lane], v[n], s);
                cb_s[(e*64 + chl)*32 + lane] = s;
            }
        }
        __syncthreads();

        // phase C: warp = head e; h_e[64d][32p] += Wv_e'^T @ cbar_e over this 64-ch chunk
        {
            const float* wvp = g_wv + ((size_t)warp*HIDDEN + cbk*64)*HDIM + dg*8;
            const float* cbb = cb_s + (warp*64)*32 + pg*8;
            #pragma unroll 4
            for (int ch = 0; ch < 64; ch++) {
                float4 w0 = *(const float4*)(wvp + (size_t)ch*HDIM);
                float4 w1 = *(const float4*)(wvp + (size_t)ch*HDIM + 4);
                float4 c0 = *(const float4*)(cbb + ch*32);
                float4 c1 = *(const float4*)(cbb + ch*32 + 4);
                float wa[8] = {w0.x, w0.y, w0.z, w0.w, w1.x, w1.y, w1.z, w1.w};
                float ca[8] = {c0.x, c0.y, c0.z, c0.w, c1.x, c1.y, c1.z, c1.w};
                #pragma unroll
                for (int i = 0; i < 8; i++)
                    #pragma unroll
                    for (int j = 0; j < 8; j++)
                        acc[i][j] = fmaf(wa[i], ca[j], acc[i][j]);
            }
        }
        __syncthreads();
    }

    // store H: g_h[e*64+d][pix]
    int pix0 = b*PIXB + h*WW + pg*8;
    #pragma unroll
    for (int i = 0; i < 8; i++) {
        float* dst = g_h + (size_t)(warp*HDIM + dg*8 + i)*NPIX + pix0;
        *(float4*)(dst)     = make_float4(acc[i][0], acc[i][1], acc[i][2], acc[i][3]);
        *(float4*)(dst + 4) = make_float4(acc[i][4], acc[i][5], acc[i][6], acc[i][7]);
    }
}

// ---------------- K4: GEMM2: out[256,8192] = W_out^T[256,512] @ H[512,8192] + b_out
__global__ __launch_bounds__(256, 2) void k_gemm2(
    const float* __restrict__ w_out, const float* __restrict__ b_out,
    float* __restrict__ out)
{
    __shared__ float sA[32*64];    // [k][co]
    __shared__ float sB[32*256];   // [k][p]
    int co0 = blockIdx.y * 64;
    int px0 = blockIdx.x * 256;
    int lane = threadIdx.x & 31, warp = threadIdx.x >> 5;

    float acc[8][8];
    #pragma unroll
    for (int i = 0; i < 8; i++)
        #pragma unroll
        for (int j = 0; j < 8; j++) acc[i][j] = 0.f;

    for (int kc = 0; kc < HS; kc += 32) {
        #pragma unroll
        for (int i = 0; i < 8; i++) {
            int idx = threadIdx.x + i*256;
            int k = idx >> 6, co = idx & 63;
            sA[idx] = w_out[(size_t)(kc + k)*HIDDEN + co0 + co];
        }
        #pragma unroll
        for (int i = 0; i < 8; i++) {
            int f4 = threadIdx.x + i*256;
            int k = f4 >> 6, p4 = f4 & 63;
            ((float4*)sB)[f4] = *(const float4*)&g_h[(size_t)(kc + k)*NPIX + px0 + p4*4];
        }
        __syncthreads();
        #pragma unroll
        for (int k = 0; k < 32; k++) {
            float aa[8], bb[8];
            *(float4*)(aa)   = *(const float4*)&sA[k*64 + warp*8];
            *(float4*)(aa+4) = *(const float4*)&sA[k*64 + warp*8 + 4];
            *(float4*)(bb)   = *(const float4*)&sB[k*256 + lane*8];
            *(float4*)(bb+4) = *(const float4*)&sB[k*256 + lane*8 + 4];
            #pragma unroll
            for (int i = 0; i < 8; i++)
                #pragma unroll
                for (int j = 0; j < 8; j++) acc[i][j] = fmaf(aa[i], bb[j], acc[i][j]);
        }
        __syncthreads();
    }
    int bb_ = px0 >> 10;           // batch of this pixel tile
    int hw  = px0 & 1023;
    #pragma unroll
    for (int i = 0; i < 8; i++) {
        int co = co0 + warp*8 + i;
        float bias = b_out[co];
        float* dst = out + ((size_t)(bb_*HIDDEN + co))*PIXB + hw + lane*8;
        *(float4*)(dst)   = make_float4(acc[i][0]+bias, acc[i][1]+bias, acc[i][2]+bias, acc[i][3]+bias);
        *(float4*)(dst+4) = make_float4(acc[i][4]+bias, acc[i][5]+bias, acc[i][6]+bias, acc[i][7]+bias);
    }
}

// ---------------- launch ----------------
extern "C" void kernel_launch(void* const* d_in, const int* in_sizes, int n_in,
                              void* d_out, int out_size)
{
    const int*   q     = (const int*)  d_in[0];
    const float* c     = (const float*)d_in[1];
    const float* rms_w = (const float*)d_in[2];
    const float* emb   = (const float*)d_in[3];
    const float* w1    = (const float*)d_in[4];
    const float* b1    = (const float*)d_in[5];
    const float* w2    = (const float*)d_in[6];
    const float* b2    = (const float*)d_in[7];
    const float* w_kv  = (const float*)d_in[8];
    const float* w_out = (const float*)d_in[9];
    const float* b_out = (const float*)d_in[10];
    float* out = (float*)d_out;

    static int smem_set = 0;
    const int ATTN_SMEM = 22784 * (int)sizeof(float);   // 91136 B
    // attribute set is idempotent & deterministic; safe under graph capture
    cudaFuncSetAttribute(k_attn2, cudaFuncAttributeMaxDynamicSharedMemorySize, ATTN_SMEM);
    (void)smem_set;

    k_qh  <<<BATCH, 512>>>(q, emb, w1, b1, w2, b2);
    k_wqc <<<dim3(NHEADS, BATCH), 256>>>(w_kv, rms_w);
    k_prep<<<HIDDEN, 512>>>(w_kv, rms_w);
    k_attn2<<<BATCH*HH, 256, ATTN_SMEM>>>(c);
    k_gemm2<<<dim3(NPIX/256, HIDDEN/64), 256>>>(w_out, b_out, out);
}

// round 4
// speedup vs baseline: 1.2696x; 1.0874x over previous
#include <cuda_runtime.h>
#include <cuda_bf16.h>
#include <math.h>

#define HIDDEN 256
#define HS     512
#define NHEADS 8
#define HDIM   64
#define NTOK   8
#define BATCH  8
#define HH     32
#define WW     32
#define PIXB   (HH*WW)        // 1024 pixels per batch
#define NPIX   (BATCH*PIXB)   // 8192
#define EPSV   1e-6f
#define ATTN_SCALE 0.125f     // 64^-0.5

typedef unsigned long long ull;

// ---- packed f32x2 helpers (FFMA2: ptxas never emits this from C++) ----
__device__ __forceinline__ ull pack2(float lo, float hi) {
    ull r; asm("mov.b64 %0, {%1, %2};" : "=l"(r) : "f"(lo), "f"(hi)); return r;
}
__device__ __forceinline__ ull splat2(float x) {
    ull r; asm("mov.b64 %0, {%1, %1};" : "=l"(r) : "f"(x)); return r;
}
__device__ __forceinline__ void unpack2(ull p, float& lo, float& hi) {
    asm("mov.b64 {%0, %1}, %2;" : "=f"(lo), "=f"(hi) : "l"(p));
}
__device__ __forceinline__ void ffma2(ull& d, ull a, ull b) {
    asm("fma.rn.f32x2 %0, %1, %2, %0;" : "+l"(d) : "l"(a), "l"(b));
}

// ---------------- device scratch ----------------
__device__ float g_qh[BATCH*HS];                 // [b][512]
__device__ float g_wqc[BATCH*NHEADS*HIDDEN];     // [b][e][256]  (scale & rms_w folded)
__device__ float g_wv[NHEADS*HIDDEN*HDIM];       // [e][ch][d]   (rms_w folded V weights)
__device__ float g_h[HS*NPIX];                   // [e*64+d][pix]

// ---------------- K0: query MLP -> qh[b][512] ----------------
__global__ __launch_bounds__(512) void k_qh(
    const int* __restrict__ q, const float* __restrict__ emb,
    const float* __restrict__ w1, const float* __restrict__ b1,
    const float* __restrict__ w2, const float* __restrict__ b2)
{
    __shared__ float qe[HIDDEN];
    __shared__ float t[HS];
    int b = blockIdx.x;
    int tid = threadIdx.x;
    if (tid < HIDDEN) qe[tid] = emb[q[b]*HIDDEN + tid];
    __syncthreads();
    float acc = b1[tid];
    #pragma unroll 8
    for (int ch = 0; ch < HIDDEN; ch++) acc = fmaf(qe[ch], w1[ch*HS + tid], acc);
    t[tid] = acc / (1.f + expf(-acc));
    __syncthreads();
    float acc2 = b2[tid];
    #pragma unroll 8
    for (int k = 0; k < HS; k++) acc2 = fmaf(t[k], w2[k*HS + tid], acc2);
    g_qh[b*HS + tid] = acc2;
}

// ---------------- K1: wqc[b][e][ch] ----------------
__global__ __launch_bounds__(256) void k_wqc(
    const float* __restrict__ w_kv, const float* __restrict__ rms_w)
{
    int e = blockIdx.x, b = blockIdx.y;
    int ch = threadIdx.x;
    __shared__ float qh_s[HDIM];
    if (ch < HDIM) qh_s[ch] = g_qh[b*HS + e*HDIM + ch];
    __syncthreads();
    const float4* wk = (const float4*)(w_kv + ch*(2*HS) + e*(2*HDIM));
    float acc = 0.f;
    #pragma unroll
    for (int d4 = 0; d4 < HDIM/4; d4++) {
        float4 w = wk[d4];
        acc = fmaf(qh_s[d4*4+0], w.x, acc);
        acc = fmaf(qh_s[d4*4+1], w.y, acc);
        acc = fmaf(qh_s[d4*4+2], w.z, acc);
        acc = fmaf(qh_s[d4*4+3], w.w, acc);
    }
    g_wqc[(b*NHEADS + e)*HIDDEN + ch] = acc * rms_w[ch] * ATTN_SCALE;
}

// ---------------- K1b: repack V weights head-major, rms_w folded ----------------
__global__ __launch_bounds__(512) void k_prep(
    const float* __restrict__ w_kv, const float* __restrict__ rms_w)
{
    int ch = blockIdx.x;
    int tid = threadIdx.x;
    int e = tid >> 6, d = tid & 63;
    g_wv[((size_t)e*HIDDEN + ch)*HDIM + d] =
        rms_w[ch] * w_kv[(size_t)ch*(2*HS) + e*(2*HDIM) + HDIM + d];
}

// ---------------- K2: fused rmsnorm + dots + softmax + cbar + V-GEMM -> g_h ----------------
// Block = one (b,h) row of 32 pixels, 256 threads (8 warps).
// Dynamic smem (bytes): swq2 ull[1024] | a2_s ull[1024] | s_s f[2048] | rms f[256]
//                       | a_s f[2048] | cb_s f[16384]   => 99328 B total
__global__ __launch_bounds__(256, 2) void k_attn2(const float* __restrict__ c)
{
    extern __shared__ ull smu[];
    ull*   swq2  = smu;              // [ch][4 head-pairs]
    ull*   a2_s  = smu + 1024;       // [n][4 head-pairs][lane]
    float* fb    = (float*)(smu + 2048);
    float* s_s   = fb;               // dots [e][n][p]
    float* rms_s = fb + 2048;        // [n][p]
    float* a_s   = fb + 2304;        // attn*inv_rms [e][n][p]
    float* cb_s  = fb + 4352;        // cbar chunk [e][64ch][32p]

    int b = blockIdx.x >> 5;
    int h = blockIdx.x & 31;
    int tid = threadIdx.x;
    int warp = tid >> 5, lane = tid & 31;

    // load wqc pair-major over heads: swq2[ch*4+p] = (wqc[2p][ch], wqc[2p+1][ch])
    for (int i = tid; i < HIDDEN*4; i += 256) {
        int ch = i >> 2, p = i & 3;
        float lo = g_wqc[b*NHEADS*HIDDEN + (2*p)*HIDDEN + ch];
        float hi = g_wqc[b*NHEADS*HIDDEN + (2*p+1)*HIDDEN + ch];
        swq2[i] = pack2(lo, hi);
    }
    __syncthreads();

    // ---- pass A: sumsq + dots (warp = token n, lane = pixel p) ----
    {
        const float* cp = c + ((size_t)(b*NTOK + warp)*HIDDEN)*PIXB + h*WW + lane;
        float ss = 0.f;
        ull sd2[4] = {0ull, 0ull, 0ull, 0ull};
        #pragma unroll 4
        for (int ch = 0; ch < HIDDEN; ch++) {
            float v = cp[(size_t)ch*PIXB];
            ss = fmaf(v, v, ss);
            ull v2 = splat2(v);
            #pragma unroll
            for (int p = 0; p < 4; p++) ffma2(sd2[p], v2, swq2[ch*4 + p]);
        }
        rms_s[warp*32 + lane] = rsqrtf(ss*(1.0f/HIDDEN) + EPSV);
        #pragma unroll
        for (int p = 0; p < 4; p++) {
            float lo, hi; unpack2(sd2[p], lo, hi);
            s_s[((2*p)*NTOK + warp)*32 + lane]   = lo;
            s_s[((2*p+1)*NTOK + warp)*32 + lane] = hi;
        }
    }
    __syncthreads();

    // ---- softmax: thread = (e = tid>>5, p = tid&31) ----
    {
        int e = tid >> 5, p = tid & 31;
        float d[NTOK], m = -1e30f;
        #pragma unroll
        for (int n = 0; n < NTOK; n++) {
            d[n] = s_s[(e*NTOK + n)*32 + p] * rms_s[n*32 + p];
            m = fmaxf(m, d[n]);
        }
        float sum = 0.f;
        #pragma unroll
        for (int n = 0; n < NTOK; n++) { d[n] = expf(d[n] - m); sum += d[n]; }
        float inv = 1.f / sum;
        #pragma unroll
        for (int n = 0; n < NTOK; n++)
            a_s[(e*NTOK + n)*32 + p] = d[n] * inv * rms_s[n*32 + p];
    }
    __syncthreads();

    // repack attn pair-major over heads: a2_s[(n*4+p)*32+lane] = (a[2p][n], a[2p+1][n])
    for (int i = tid; i < 1024; i += 256) {
        int n = i >> 7, p = (i >> 5) & 3, l2 = i & 31;
        float lo = a_s[((2*p)*NTOK + n)*32 + l2];
        float hi = a_s[((2*p+1)*NTOK + n)*32 + l2];
        a2_s[i] = pack2(lo, hi);
    }
    __syncthreads();

    // ---- chunked cbar + per-head V-GEMM ----
    // GEMM layout: warp = head e, lane = (dg = lane>>2, pg = lane&3); acc d=dg*8+i, p=pg*8+{2j,2j+1}
    int dg = lane >> 2, pg = lane & 3;
    ull acc2[8][4];
    #pragma unroll
    for (int i = 0; i < 8; i++)
        #pragma unroll
        for (int j = 0; j < 4; j++) acc2[i][j] = 0ull;

    for (int cbk = 0; cbk < 4; cbk++) {
        // phase B: cbar chunk — warp covers 8 channels, all 8 heads via 4 pairs
        #pragma unroll
        for (int cc = 0; cc < 8; cc++) {
            int chl = warp*8 + cc;
            int ch  = cbk*64 + chl;
            const float* cp = c + ((size_t)(b*NTOK)*HIDDEN + ch)*PIXB + h*WW + lane;
            float v[NTOK];
            #pragma unroll
            for (int n = 0; n < NTOK; n++) v[n] = cp[(size_t)n*HIDDEN*PIXB];
            ull cb2[4] = {0ull, 0ull, 0ull, 0ull};
            #pragma unroll
            for (int n = 0; n < NTOK; n++) {
                ull v2 = splat2(v[n]);
                #pragma unroll
                for (int p = 0; p < 4; p++) ffma2(cb2[p], v2, a2_s[(n*4 + p)*32 + lane]);
            }
            #pragma unroll
            for (int p = 0; p < 4; p++) {
                float lo, hi; unpack2(cb2[p], lo, hi);
                cb_s[((2*p)*64 + chl)*32 + lane]   = lo;
                cb_s[((2*p+1)*64 + chl)*32 + lane] = hi;
            }
        }
        __syncthreads();

        // phase C: warp = head e; acc += Wv'^T @ cbar_e over this 64-ch chunk
        {
            const float* wvp = g_wv + ((size_t)warp*HIDDEN + cbk*64)*HDIM + dg*8;
            const float* cbb = cb_s + (warp*64)*32 + pg*8;
            #pragma unroll 4
            for (int ch = 0; ch < 64; ch++) {
                float4 w0 = *(const float4*)(wvp + (size_t)ch*HDIM);
                float4 w1 = *(const float4*)(wvp + (size_t)ch*HDIM + 4);
                float4 c0 = *(const float4*)(cbb + ch*32);
                float4 c1 = *(const float4*)(cbb + ch*32 + 4);
                ull bb[4] = {pack2(c0.x, c0.y), pack2(c0.z, c0.w),
                             pack2(c1.x, c1.y), pack2(c1.z, c1.w)};
                ull as[8] = {splat2(w0.x), splat2(w0.y), splat2(w0.z), splat2(w0.w),
                             splat2(w1.x), splat2(w1.y), splat2(w1.z), splat2(w1.w)};
                #pragma unroll
                for (int i = 0; i < 8; i++)
                    #pragma unroll
                    for (int j = 0; j < 4; j++) ffma2(acc2[i][j], as[i], bb[j]);
            }
        }
        __syncthreads();
    }

    // store H: g_h[e*64+d][pix]
    int pix0 = b*PIXB + h*WW + pg*8;
    #pragma unroll
    for (int i = 0; i < 8; i++) {
        float r[8];
        #pragma unroll
        for (int j = 0; j < 4; j++) unpack2(acc2[i][j], r[2*j], r[2*j+1]);
        float* dst = g_h + (size_t)(warp*HDIM + dg*8 + i)*NPIX + pix0;
        *(float4*)(dst)     = make_float4(r[0], r[1], r[2], r[3]);
        *(float4*)(dst + 4) = make_float4(r[4], r[5], r[6], r[7]);
    }
}

// ---------------- K4: GEMM2: out[256,8192] = W_out^T @ H + b_out ----------------
__global__ __launch_bounds__(256, 2) void k_gemm2(
    const float* __restrict__ w_out, const float* __restrict__ b_out,
    float* __restrict__ out)
{
    __shared__ float sA[32*64];    // [k][co]
    __shared__ float sB[32*256];   // [k][p]
    int co0 = blockIdx.y * 64;
    int px0 = blockIdx.x * 256;
    int lane = threadIdx.x & 31, warp = threadIdx.x >> 5;

    ull acc2[8][4];
    #pragma unroll
    for (int i = 0; i < 8; i++)
        #pragma unroll
        for (int j = 0; j < 4; j++) acc2[i][j] = 0ull;

    for (int kc = 0; kc < HS; kc += 32) {
        #pragma unroll
        for (int i = 0; i < 8; i++) {
            int idx = threadIdx.x + i*256;
            int k = idx >> 6, co = idx & 63;
            sA[idx] = w_out[(size_t)(kc + k)*HIDDEN + co0 + co];
        }
        #pragma unroll
        for (int i = 0; i < 8; i++) {
            int f4 = threadIdx.x + i*256;
            int k = f4 >> 6, p4 = f4 & 63;
            ((float4*)sB)[f4] = *(const float4*)&g_h[(size_t)(kc + k)*NPIX + px0 + p4*4];
        }
        __syncthreads();
        #pragma unroll
        for (int k = 0; k < 32; k++) {
            float4 a0 = *(const float4*)&sA[k*64 + warp*8];
            float4 a1 = *(const float4*)&sA[k*64 + warp*8 + 4];
            float4 b0 = *(const float4*)&sB[k*256 + lane*8];
            float4 b1 = *(const float4*)&sB[k*256 + lane*8 + 4];
            ull bb[4] = {pack2(b0.x, b0.y), pack2(b0.z, b0.w),
                         pack2(b1.x, b1.y), pack2(b1.z, b1.w)};
            ull as[8] = {splat2(a0.x), splat2(a0.y), splat2(a0.z), splat2(a0.w),
                         splat2(a1.x), splat2(a1.y), splat2(a1.z), splat2(a1.w)};
            #pragma unroll
            for (int i = 0; i < 8; i++)
                #pragma unroll
                for (int j = 0; j < 4; j++) ffma2(acc2[i][j], as[i], bb[j]);
        }
        __syncthreads();
    }
    int bb_ = px0 >> 10;           // batch of this pixel tile
    int hw  = px0 & 1023;
    #pragma unroll
    for (int i = 0; i < 8; i++) {
        int co = co0 + warp*8 + i;
        float bias = b_out[co];
        float r[8];
        #pragma unroll
        for (int j = 0; j < 4; j++) unpack2(acc2[i][j], r[2*j], r[2*j+1]);
        float* dst = out + ((size_t)(bb_*HIDDEN + co))*PIXB + hw + lane*8;
        *(float4*)(dst)   = make_float4(r[0]+bias, r[1]+bias, r[2]+bias, r[3]+bias);
        *(float4*)(dst+4) = make_float4(r[4]+bias, r[5]+bias, r[6]+bias, r[7]+bias);
    }
}

// ---------------- launch ----------------
extern "C" void kernel_launch(void* const* d_in, const int* in_sizes, int n_in,
                              void* d_out, int out_size)
{
    const int*   q     = (const int*)  d_in[0];
    const float* c     = (const float*)d_in[1];
    const float* rms_w = (const float*)d_in[2];
    const float* emb   = (const float*)d_in[3];
    const float* w1    = (const float*)d_in[4];
    const float* b1    = (const float*)d_in[5];
    const float* w2    = (const float*)d_in[6];
    const float* b2    = (const float*)d_in[7];
    const float* w_kv  = (const float*)d_in[8];
    const float* w_out = (const float*)d_in[9];
    const float* b_out = (const float*)d_in[10];
    float* out = (float*)d_out;

    const int ATTN_SMEM = 99328;   // bytes, see k_attn2 layout
    cudaFuncSetAttribute(k_attn2, cudaFuncAttributeMaxDynamicSharedMemorySize, ATTN_SMEM);

    k_qh   <<<BATCH, 512>>>(q, emb, w1, b1, w2, b2);
    k_wqc  <<<dim3(NHEADS, BATCH), 256>>>(w_kv, rms_w);
    k_prep <<<HIDDEN, 512>>>(w_kv, rms_w);
    k_attn2<<<BATCH*HH, 256, ATTN_SMEM>>>(c);
    k_gemm2<<<dim3(NPIX/256, HIDDEN/64), 256>>>(w_out, b_out, out);
}

// round 5
// speedup vs baseline: 1.7115x; 1.3481x over previous
#include <cuda_runtime.h>
#include <cuda_bf16.h>
#include <math.h>

#define HIDDEN 256
#define HS     512
#define NHEADS 8
#define HDIM   64
#define NTOK   8
#define BATCH  8
#define HH     32
#define WW     32
#define PIXB   (HH*WW)        // 1024 pixels per batch
#define NPIX   (BATCH*PIXB)   // 8192
#define EPSV   1e-6f
#define ATTN_SCALE 0.125f     // 64^-0.5

typedef unsigned long long ull;

// ---- packed f32x2 helpers (FFMA2: ptxas never emits this from C++) ----
__device__ __forceinline__ ull pack2(float lo, float hi) {
    ull r; asm("mov.b64 %0, {%1, %2};" : "=l"(r) : "f"(lo), "f"(hi)); return r;
}
__device__ __forceinline__ ull splat2(float x) {
    ull r; asm("mov.b64 %0, {%1, %1};" : "=l"(r) : "f"(x)); return r;
}
__device__ __forceinline__ void unpack2(ull p, float& lo, float& hi) {
    asm("mov.b64 {%0, %1}, %2;" : "=f"(lo), "=f"(hi) : "l"(p));
}
__device__ __forceinline__ void ffma2(ull& d, ull a, ull b) {
    asm("fma.rn.f32x2 %0, %1, %2, %0;" : "+l"(d) : "l"(a), "l"(b));
}

// ---------------- device scratch ----------------
__device__ float g_qh[BATCH*HS];                 // [b][512]
__device__ float g_wqc[BATCH*NHEADS*HIDDEN];     // [b][e][256]  (scale & rms_w folded)
__device__ float g_wv[NHEADS*HIDDEN*HDIM];       // [e][ch][d]   (rms_w folded V weights)
__device__ float g_h[HS*NPIX];                   // [e*64+d][pix]

// ---------------- K0: query MLP -> qh[b][512] ----------------
__global__ __launch_bounds__(512) void k_qh(
    const int* __restrict__ q, const float* __restrict__ emb,
    const float* __restrict__ w1, const float* __restrict__ b1,
    const float* __restrict__ w2, const float* __restrict__ b2)
{
    __shared__ float qe[HIDDEN];
    __shared__ float t[HS];
    int b = blockIdx.x;
    int tid = threadIdx.x;
    if (tid < HIDDEN) qe[tid] = emb[q[b]*HIDDEN + tid];
    __syncthreads();
    float acc = b1[tid];
    #pragma unroll 1
    for (int ch0 = 0; ch0 < HIDDEN; ch0 += 16) {
        float v[16];
        #pragma unroll
        for (int u = 0; u < 16; u++) v[u] = w1[(ch0+u)*HS + tid];
        #pragma unroll
        for (int u = 0; u < 16; u++) acc = fmaf(qe[ch0+u], v[u], acc);
    }
    t[tid] = acc / (1.f + expf(-acc));
    __syncthreads();
    float acc2 = b2[tid];
    #pragma unroll 1
    for (int k0 = 0; k0 < HS; k0 += 16) {
        float v[16];
        #pragma unroll
        for (int u = 0; u < 16; u++) v[u] = w2[(k0+u)*HS + tid];
        #pragma unroll
        for (int u = 0; u < 16; u++) acc2 = fmaf(t[k0+u], v[u], acc2);
    }
    g_qh[b*HS + tid] = acc2;
}

// ---------------- K1: merged wqc + V-weight repack ----------------
// blocks [0,256): g_wv[e][ch][d] = rms_w[ch]*w_kv[ch][e*128+64+d]
// blocks [256,320): wqc[b][e][ch] (K weights folded with qh, rms_w, scale)
__global__ __launch_bounds__(512) void k_prep2(
    const float* __restrict__ w_kv, const float* __restrict__ rms_w)
{
    __shared__ float qh_s[HDIM];
    if (blockIdx.x < HIDDEN) {
        int ch = blockIdx.x;
        int tid = threadIdx.x;
        int e = tid >> 6, d = tid & 63;
        g_wv[((size_t)e*HIDDEN + ch)*HDIM + d] =
            rms_w[ch] * w_kv[(size_t)ch*(2*HS) + e*(2*HDIM) + HDIM + d];
    } else {
        int idx = blockIdx.x - HIDDEN;     // 0..63
        int e = idx & 7, b = idx >> 3;
        int tid = threadIdx.x;
        if (tid < HDIM) qh_s[tid] = g_qh[b*HS + e*HDIM + tid];
        __syncthreads();
        if (tid < HIDDEN) {
            int ch = tid;
            const float4* wk = (const float4*)(w_kv + ch*(2*HS) + e*(2*HDIM));
            float acc = 0.f;
            #pragma unroll
            for (int d4 = 0; d4 < HDIM/4; d4++) {
                float4 w = wk[d4];
                acc = fmaf(qh_s[d4*4+0], w.x, acc);
                acc = fmaf(qh_s[d4*4+1], w.y, acc);
                acc = fmaf(qh_s[d4*4+2], w.z, acc);
                acc = fmaf(qh_s[d4*4+3], w.w, acc);
            }
            g_wqc[(b*NHEADS + e)*HIDDEN + ch] = acc * rms_w[ch] * ATTN_SCALE;
        }
    }
}

// ---------------- K2: fused rmsnorm + dots + softmax + cbar + V-GEMM -> g_h ----------------
// Block = one (b,h) row of 32 pixels, 256 threads (8 warps).
// Dynamic smem: swq2 ull[1024] | a2_s ull[1024] | s_s f[2048] | rms f[256]
//               | a_s f[2048] | cb_s f[16384]   => 99328 B
__global__ __launch_bounds__(256, 2) void k_attn2(const float* __restrict__ c)
{
    extern __shared__ ull smu[];
    ull*   swq2  = smu;              // [ch][4 head-pairs]
    ull*   a2_s  = smu + 1024;       // [n][4 head-pairs][lane]
    float* fb    = (float*)(smu + 2048);
    float* s_s   = fb;               // dots [e][n][p]
    float* rms_s = fb + 2048;        // [n][p]
    float* a_s   = fb + 2304;        // attn*inv_rms [e][n][p]
    float* cb_s  = fb + 4352;        // cbar chunk [e][64ch][32p]

    int b = blockIdx.x >> 5;
    int h = blockIdx.x & 31;
    int tid = threadIdx.x;
    int warp = tid >> 5, lane = tid & 31;

    // wqc pair-major over heads: swq2[ch*4+p] = (wqc[2p][ch], wqc[2p+1][ch])
    for (int i = tid; i < HIDDEN*4; i += 256) {
        int ch = i >> 2, p = i & 3;
        float lo = g_wqc[b*NHEADS*HIDDEN + (2*p)*HIDDEN + ch];
        float hi = g_wqc[b*NHEADS*HIDDEN + (2*p+1)*HIDDEN + ch];
        swq2[i] = pack2(lo, hi);
    }
    __syncthreads();

    // ---- pass A: sumsq + dots (warp = token n, lane = pixel p), MLP=16 ----
    {
        const float* cp = c + ((size_t)(b*NTOK + warp)*HIDDEN)*PIXB + h*WW + lane;
        float ss = 0.f;
        ull sd2[4] = {0ull, 0ull, 0ull, 0ull};
        #pragma unroll 1
        for (int ch0 = 0; ch0 < HIDDEN; ch0 += 16) {
            float v[16];
            #pragma unroll
            for (int u = 0; u < 16; u++) v[u] = cp[(size_t)(ch0+u)*PIXB];
            #pragma unroll
            for (int u = 0; u < 16; u++) {
                int ch = ch0 + u;
                ss = fmaf(v[u], v[u], ss);
                ull v2 = splat2(v[u]);
                ulonglong2 s01 = *(const ulonglong2*)(swq2 + ch*4);
                ulonglong2 s23 = *(const ulonglong2*)(swq2 + ch*4 + 2);
                ffma2(sd2[0], v2, s01.x);
                ffma2(sd2[1], v2, s01.y);
                ffma2(sd2[2], v2, s23.x);
                ffma2(sd2[3], v2, s23.y);
            }
        }
        rms_s[warp*32 + lane] = rsqrtf(ss*(1.0f/HIDDEN) + EPSV);
        #pragma unroll
        for (int p = 0; p < 4; p++) {
            float lo, hi; unpack2(sd2[p], lo, hi);
            s_s[((2*p)*NTOK + warp)*32 + lane]   = lo;
            s_s[((2*p+1)*NTOK + warp)*32 + lane] = hi;
        }
    }
    __syncthreads();

    // ---- softmax: thread = (e = tid>>5, p = tid&31) ----
    {
        int e = tid >> 5, p = tid & 31;
        float d[NTOK], m = -1e30f;
        #pragma unroll
        for (int n = 0; n < NTOK; n++) {
            d[n] = s_s[(e*NTOK + n)*32 + p] * rms_s[n*32 + p];
            m = fmaxf(m, d[n]);
        }
        float sum = 0.f;
        #pragma unroll
        for (int n = 0; n < NTOK; n++) { d[n] = expf(d[n] - m); sum += d[n]; }
        float inv = 1.f / sum;
        #pragma unroll
        for (int n = 0; n < NTOK; n++)
            a_s[(e*NTOK + n)*32 + p] = d[n] * inv * rms_s[n*32 + p];
    }
    __syncthreads();

    // repack attn pair-major: a2_s[(n*4+p)*32+lane] = (a[2p][n], a[2p+1][n])
    for (int i = tid; i < 1024; i += 256) {
        int n = i >> 7, p = (i >> 5) & 3, l2 = i & 31;
        float lo = a_s[((2*p)*NTOK + n)*32 + l2];
        float hi = a_s[((2*p+1)*NTOK + n)*32 + l2];
        a2_s[i] = pack2(lo, hi);
    }
    __syncthreads();

    // ---- chunked cbar + per-head V-GEMM ----
    int dg = lane >> 2, pg = lane & 3;
    ull acc2[8][4];
    #pragma unroll
    for (int i = 0; i < 8; i++)
        #pragma unroll
        for (int j = 0; j < 4; j++) acc2[i][j] = 0ull;

    for (int cbk = 0; cbk < 4; cbk++) {
        // phase B: cbar chunk — warp covers 8 channels, all 8 heads via 4 pairs
        #pragma unroll
        for (int cc = 0; cc < 8; cc++) {
            int chl = warp*8 + cc;
            int ch  = cbk*64 + chl;
            const float* cp = c + ((size_t)(b*NTOK)*HIDDEN + ch)*PIXB + h*WW + lane;
            float v[NTOK];
            #pragma unroll
            for (int n = 0; n < NTOK; n++) v[n] = cp[(size_t)n*HIDDEN*PIXB];
            ull cb2[4] = {0ull, 0ull, 0ull, 0ull};
            #pragma unroll
            for (int n = 0; n < NTOK; n++) {
                ull v2 = splat2(v[n]);
                ffma2(cb2[0], v2, a2_s[(n*4 + 0)*32 + lane]);
                ffma2(cb2[1], v2, a2_s[(n*4 + 1)*32 + lane]);
                ffma2(cb2[2], v2, a2_s[(n*4 + 2)*32 + lane]);
                ffma2(cb2[3], v2, a2_s[(n*4 + 3)*32 + lane]);
            }
            #pragma unroll
            for (int p = 0; p < 4; p++) {
                float lo, hi; unpack2(cb2[p], lo, hi);
                cb_s[((2*p)*64 + chl)*32 + lane]   = lo;
                cb_s[((2*p+1)*64 + chl)*32 + lane] = hi;
            }
        }
        __syncthreads();

        // phase C: warp = head e; acc += Wv'^T @ cbar_e over this 64-ch chunk
        {
            const float* wvp = g_wv + ((size_t)warp*HIDDEN + cbk*64)*HDIM + dg*8;
            const float* cbb = cb_s + (warp*64)*32 + pg*8;
            #pragma unroll 4
            for (int ch = 0; ch < 64; ch++) {
                float4 w0 = *(const float4*)(wvp + (size_t)ch*HDIM);
                float4 w1 = *(const float4*)(wvp + (size_t)ch*HDIM + 4);
                ulonglong2 c01 = *(const ulonglong2*)(cbb + ch*32);
                ulonglong2 c23 = *(const ulonglong2*)(cbb + ch*32 + 4);
                ull bb0 = c01.x, bb1 = c01.y, bb2 = c23.x, bb3 = c23.y;
                ull as[8] = {splat2(w0.x), splat2(w0.y), splat2(w0.z), splat2(w0.w),
                             splat2(w1.x), splat2(w1.y), splat2(w1.z), splat2(w1.w)};
                #pragma unroll
                for (int i = 0; i < 8; i++) {
                    ffma2(acc2[i][0], as[i], bb0);
                    ffma2(acc2[i][1], as[i], bb1);
                    ffma2(acc2[i][2], as[i], bb2);
                    ffma2(acc2[i][3], as[i], bb3);
                }
            }
        }
        __syncthreads();
    }

    // store H: g_h[e*64+d][pix]
    int pix0 = b*PIXB + h*WW + pg*8;
    #pragma unroll
    for (int i = 0; i < 8; i++) {
        float r[8];
        #pragma unroll
        for (int j = 0; j < 4; j++) unpack2(acc2[i][j], r[2*j], r[2*j+1]);
        float* dst = g_h + (size_t)(warp*HDIM + dg*8 + i)*NPIX + pix0;
        *(float4*)(dst)     = make_float4(r[0], r[1], r[2], r[3]);
        *(float4*)(dst + 4) = make_float4(r[4], r[5], r[6], r[7]);
    }
}

// ---------------- K4: GEMM2: out[256,8192] = W_out^T @ H + b_out ----------------
// Tile 64co x 128px, grid (64,4)=256 blocks, 256 threads.
// Thread: co = co0 + warp*8 + {0..7} (4 pairs, direct from smem), px = px0 + lane*4 + {0..3} (splats)
__global__ __launch_bounds__(256, 2) void k_gemm2(
    const float* __restrict__ w_out, const float* __restrict__ b_out,
    float* __restrict__ out)
{
    __shared__ float sA[32*64];    // [k][co]
    __shared__ float sB[32*128];   // [k][p]
    int co0 = blockIdx.y * 64;
    int px0 = blockIdx.x * 128;
    int lane = threadIdx.x & 31, warp = threadIdx.x >> 5;

    ull acc2[4][4];   // [co-pair][px]
    #pragma unroll
    for (int i = 0; i < 4; i++)
        #pragma unroll
        for (int j = 0; j < 4; j++) acc2[i][j] = 0ull;

    for (int kc = 0; kc < HS; kc += 32) {
        #pragma unroll
        for (int i = 0; i < 2; i++) {
            int f4 = threadIdx.x + i*256;      // 0..511
            int k = f4 >> 4, c4 = f4 & 15;
            ((float4*)sA)[f4] = *(const float4*)&w_out[(size_t)(kc + k)*HIDDEN + co0 + c4*4];
        }
        #pragma unroll
        for (int i = 0; i < 4; i++) {
            int f4 = threadIdx.x + i*256;      // 0..1023
            int k = f4 >> 5, p4 = f4 & 31;
            ((float4*)sB)[f4] = *(const float4*)&g_h[(size_t)(kc + k)*NPIX + px0 + p4*4];
        }
        __syncthreads();
        #pragma unroll
        for (int k = 0; k < 32; k++) {
            ulonglong2 a01 = *(const ulonglong2*)&sA[k*64 + warp*8];
            ulonglong2 a23 = *(const ulonglong2*)&sA[k*64 + warp*8 + 4];
            float4 bv = *(const float4*)&sB[k*128 + lane*4];
            ull aa[4] = {a01.x, a01.y, a23.x, a23.y};
            ull b0 = splat2(bv.x), b1 = splat2(bv.y), b2 = splat2(bv.z), b3 = splat2(bv.w);
            #pragma unroll
            for (int i = 0; i < 4; i++) {
                ffma2(acc2[i][0], aa[i], b0);
                ffma2(acc2[i][1], aa[i], b1);
                ffma2(acc2[i][2], aa[i], b2);
                ffma2(acc2[i][3], aa[i], b3);
            }
        }
        __syncthreads();
    }
    int b_ = px0 >> 10;
    int hw = px0 & 1023;
    #pragma unroll
    for (int i = 0; i < 4; i++) {
        float lo[4], hi[4];
        #pragma unroll
        for (int j = 0; j < 4; j++) unpack2(acc2[i][j], lo[j], hi[j]);
        int co_lo = co0 + warp*8 + 2*i;
        float bl = b_out[co_lo], bh = b_out[co_lo + 1];
        float* d0 = out + ((size_t)(b_*HIDDEN + co_lo))*PIXB + hw + lane*4;
        float* d1 = out + ((size_t)(b_*HIDDEN + co_lo + 1))*PIXB + hw + lane*4;
        *(float4*)d0 = make_float4(lo[0]+bl, lo[1]+bl, lo[2]+bl, lo[3]+bl);
        *(float4*)d1 = make_float4(hi[0]+bh, hi[1]+bh, hi[2]+bh, hi[3]+bh);
    }
}

// ---------------- launch ----------------
extern "C" void kernel_launch(void* const* d_in, const int* in_sizes, int n_in,
                              void* d_out, int out_size)
{
    const int*   q     = (const int*)  d_in[0];
    const float* c     = (const float*)d_in[1];
    const float* rms_w = (const float*)d_in[2];
    const float* emb   = (const float*)d_in[3];
    const float* w1    = (const float*)d_in[4];
    const float* b1    = (const float*)d_in[5];
    const float* w2    = (const float*)d_in[6];
    const float* b2    = (const float*)d_in[7];
    const float* w_kv  = (const float*)d_in[8];
    const float* w_out = (const float*)d_in[9];
    const float* b_out = (const float*)d_in[10];
    float* out = (float*)d_out;

    const int ATTN_SMEM = 99328;   // bytes, see k_attn2 layout
    cudaFuncSetAttribute(k_attn2, cudaFuncAttributeMaxDynamicSharedMemorySize, ATTN_SMEM);

    k_qh   <<<BATCH, 512>>>(q, emb, w1, b1, w2, b2);
    k_prep2<<<HIDDEN + NHEADS*BATCH, 512>>>(w_kv, rms_w);
    k_attn2<<<BATCH*HH, 256, ATTN_SMEM>>>(c);
    k_gemm2<<<dim3(NPIX/128, HIDDEN/64), 256>>>(w_out, b_out, out);
}

// round 6
// speedup vs baseline: 1.7775x; 1.0385x over previous
#include <cuda_runtime.h>
#include <cuda_bf16.h>
#include <math.h>

#define HIDDEN 256
#define HS     512
#define NHEADS 8
#define HDIM   64
#define NTOK   8
#define BATCH  8
#define HH     32
#define WW     32
#define PIXB   (HH*WW)        // 1024 pixels per batch
#define NPIX   (BATCH*PIXB)   // 8192
#define EPSV   1e-6f
#define ATTN_SCALE 0.125f     // 64^-0.5

typedef unsigned long long ull;

// ---- packed f32x2 helpers (FFMA2: ptxas never emits this from C++) ----
__device__ __forceinline__ ull pack2(float lo, float hi) {
    ull r; asm("mov.b64 %0, {%1, %2};" : "=l"(r) : "f"(lo), "f"(hi)); return r;
}
__device__ __forceinline__ ull splat2(float x) {
    ull r; asm("mov.b64 %0, {%1, %1};" : "=l"(r) : "f"(x)); return r;
}
__device__ __forceinline__ void unpack2(ull p, float& lo, float& hi) {
    asm("mov.b64 {%0, %1}, %2;" : "=f"(lo), "=f"(hi) : "l"(p));
}
__device__ __forceinline__ void ffma2(ull& d, ull a, ull b) {
    asm("fma.rn.f32x2 %0, %1, %2, %0;" : "+l"(d) : "l"(a), "l"(b));
}

// ---------------- device scratch ----------------
__device__ float g_qh[BATCH*HS];                 // [b][512]
__device__ float g_wqc[BATCH*NHEADS*HIDDEN];     // [b][e][256]  (scale & rms_w folded)
__device__ float g_wv[NHEADS*HIDDEN*HDIM];       // [e][ch][d]   (rms_w folded V weights)

// ---------------- K0: query MLP -> qh[b][512] ----------------
__global__ __launch_bounds__(512) void k_qh(
    const int* __restrict__ q, const float* __restrict__ emb,
    const float* __restrict__ w1, const float* __restrict__ b1,
    const float* __restrict__ w2, const float* __restrict__ b2)
{
    __shared__ float qe[HIDDEN];
    __shared__ float t[HS];
    int b = blockIdx.x;
    int tid = threadIdx.x;
    if (tid < HIDDEN) qe[tid] = emb[q[b]*HIDDEN + tid];
    __syncthreads();
    float acc = b1[tid];
    #pragma unroll 1
    for (int ch0 = 0; ch0 < HIDDEN; ch0 += 32) {
        float v[32];
        #pragma unroll
        for (int u = 0; u < 32; u++) v[u] = w1[(ch0+u)*HS + tid];
        #pragma unroll
        for (int u = 0; u < 32; u++) acc = fmaf(qe[ch0+u], v[u], acc);
    }
    t[tid] = acc / (1.f + expf(-acc));
    __syncthreads();
    float acc2 = b2[tid];
    #pragma unroll 1
    for (int k0 = 0; k0 < HS; k0 += 32) {
        float v[32];
        #pragma unroll
        for (int u = 0; u < 32; u++) v[u] = w2[(k0+u)*HS + tid];
        #pragma unroll
        for (int u = 0; u < 32; u++) acc2 = fmaf(t[k0+u], v[u], acc2);
    }
    g_qh[b*HS + tid] = acc2;
}

// ---------------- K1: merged wqc + V-weight repack ----------------
__global__ __launch_bounds__(512) void k_prep2(
    const float* __restrict__ w_kv, const float* __restrict__ rms_w)
{
    __shared__ float qh_s[HDIM];
    if (blockIdx.x < HIDDEN) {
        int ch = blockIdx.x;
        int tid = threadIdx.x;
        int e = tid >> 6, d = tid & 63;
        g_wv[((size_t)e*HIDDEN + ch)*HDIM + d] =
            rms_w[ch] * w_kv[(size_t)ch*(2*HS) + e*(2*HDIM) + HDIM + d];
    } else {
        int idx = blockIdx.x - HIDDEN;     // 0..63
        int e = idx & 7, b = idx >> 3;
        int tid = threadIdx.x;
        if (tid < HDIM) qh_s[tid] = g_qh[b*HS + e*HDIM + tid];
        __syncthreads();
        if (tid < HIDDEN) {
            int ch = tid;
            const float4* wk = (const float4*)(w_kv + ch*(2*HS) + e*(2*HDIM));
            float acc = 0.f;
            #pragma unroll
            for (int d4 = 0; d4 < HDIM/4; d4++) {
                float4 w = wk[d4];
                acc = fmaf(qh_s[d4*4+0], w.x, acc);
                acc = fmaf(qh_s[d4*4+1], w.y, acc);
                acc = fmaf(qh_s[d4*4+2], w.z, acc);
                acc = fmaf(qh_s[d4*4+3], w.w, acc);
            }
            g_wqc[(b*NHEADS + e)*HIDDEN + ch] = acc * rms_w[ch] * ATTN_SCALE;
        }
    }
}

// ---------------- K2: FULLY FUSED: rmsnorm + dots + softmax + cbar + V-GEMM + out-GEMM ----------------
// Block = one (b,h) row of 32 pixels, 256 threads (8 warps).
// smem (99328 B):
//   region P (33792 B): swq2 ull[1024] | a2_s ull[1024] | s_s f[2048] | rms f[256] | a_s f[2048]
//        -> reused after phase C as sW f[32*256] (32768 B)
//   region Q (65536 B): cb_s f[8h*64ch*32p]
//        -> reused after phase C as hs f[512][32]
__global__ __launch_bounds__(256, 2) void k_attn3(
    const float* __restrict__ c,
    const float* __restrict__ w_out, const float* __restrict__ b_out,
    float* __restrict__ out)
{
    extern __shared__ ull smu[];
    ull*   swq2  = smu;              // [ch][4 head-pairs]
    ull*   a2_s  = smu + 1024;       // [n][4 head-pairs][lane]
    float* fb    = (float*)(smu + 2048);
    float* s_s   = fb;               // dots [e][n][p]
    float* rms_s = fb + 2048;        // [n][p]
    float* a_s   = fb + 2304;        // attn*inv_rms [e][n][p]
    float* cb_s  = fb + 4352;        // cbar chunk [e][64ch][32p]
    float* sW    = (float*)smu;      // overlay: w_out chunk [32k][256co]
    float* hs    = cb_s;             // overlay: H [512d][32px]

    int b = blockIdx.x >> 5;
    int h = blockIdx.x & 31;
    int tid = threadIdx.x;
    int warp = tid >> 5, lane = tid & 31;

    // wqc pair-major over heads
    for (int i = tid; i < HIDDEN*4; i += 256) {
        int ch = i >> 2, p = i & 3;
        float lo = g_wqc[b*NHEADS*HIDDEN + (2*p)*HIDDEN + ch];
        float hi = g_wqc[b*NHEADS*HIDDEN + (2*p+1)*HIDDEN + ch];
        swq2[i] = pack2(lo, hi);
    }
    __syncthreads();

    // ---- pass A: sumsq + dots (warp = token n, lane = pixel p), MLP=16 ----
    {
        const float* cp = c + ((size_t)(b*NTOK + warp)*HIDDEN)*PIXB + h*WW + lane;
        float ss = 0.f;
        ull sd2[4] = {0ull, 0ull, 0ull, 0ull};
        #pragma unroll 1
        for (int ch0 = 0; ch0 < HIDDEN; ch0 += 16) {
            float v[16];
            #pragma unroll
            for (int u = 0; u < 16; u++) v[u] = cp[(size_t)(ch0+u)*PIXB];
            #pragma unroll
            for (int u = 0; u < 16; u++) {
                int ch = ch0 + u;
                ss = fmaf(v[u], v[u], ss);
                ull v2 = splat2(v[u]);
                ulonglong2 s01 = *(const ulonglong2*)(swq2 + ch*4);
                ulonglong2 s23 = *(const ulonglong2*)(swq2 + ch*4 + 2);
                ffma2(sd2[0], v2, s01.x);
                ffma2(sd2[1], v2, s01.y);
                ffma2(sd2[2], v2, s23.x);
                ffma2(sd2[3], v2, s23.y);
            }
        }
        rms_s[warp*32 + lane] = rsqrtf(ss*(1.0f/HIDDEN) + EPSV);
        #pragma unroll
        for (int p = 0; p < 4; p++) {
            float lo, hi; unpack2(sd2[p], lo, hi);
            s_s[((2*p)*NTOK + warp)*32 + lane]   = lo;
            s_s[((2*p+1)*NTOK + warp)*32 + lane] = hi;
        }
    }
    __syncthreads();

    // ---- softmax ----
    {
        int e = tid >> 5, p = tid & 31;
        float d[NTOK], m = -1e30f;
        #pragma unroll
        for (int n = 0; n < NTOK; n++) {
            d[n] = s_s[(e*NTOK + n)*32 + p] * rms_s[n*32 + p];
            m = fmaxf(m, d[n]);
        }
        float sum = 0.f;
        #pragma unroll
        for (int n = 0; n < NTOK; n++) { d[n] = expf(d[n] - m); sum += d[n]; }
        float inv = 1.f / sum;
        #pragma unroll
        for (int n = 0; n < NTOK; n++)
            a_s[(e*NTOK + n)*32 + p] = d[n] * inv * rms_s[n*32 + p];
    }
    __syncthreads();

    // repack attn pair-major
    for (int i = tid; i < 1024; i += 256) {
        int n = i >> 7, p = (i >> 5) & 3, l2 = i & 31;
        float lo = a_s[((2*p)*NTOK + n)*32 + l2];
        float hi = a_s[((2*p+1)*NTOK + n)*32 + l2];
        a2_s[i] = pack2(lo, hi);
    }
    __syncthreads();

    // ---- chunked cbar + per-head V-GEMM ----
    int dg = lane >> 2, pg = lane & 3;
    ull acc2[8][4];
    #pragma unroll
    for (int i = 0; i < 8; i++)
        #pragma unroll
        for (int j = 0; j < 4; j++) acc2[i][j] = 0ull;

    for (int cbk = 0; cbk < 4; cbk++) {
        // phase B: cbar chunk
        #pragma unroll
        for (int cc = 0; cc < 8; cc++) {
            int chl = warp*8 + cc;
            int ch  = cbk*64 + chl;
            const float* cp = c + ((size_t)(b*NTOK)*HIDDEN + ch)*PIXB + h*WW + lane;
            float v[NTOK];
            #pragma unroll
            for (int n = 0; n < NTOK; n++) v[n] = cp[(size_t)n*HIDDEN*PIXB];
            ull cb2[4] = {0ull, 0ull, 0ull, 0ull};
            #pragma unroll
            for (int n = 0; n < NTOK; n++) {
                ull v2 = splat2(v[n]);
                ffma2(cb2[0], v2, a2_s[(n*4 + 0)*32 + lane]);
                ffma2(cb2[1], v2, a2_s[(n*4 + 1)*32 + lane]);
                ffma2(cb2[2], v2, a2_s[(n*4 + 2)*32 + lane]);
                ffma2(cb2[3], v2, a2_s[(n*4 + 3)*32 + lane]);
            }
            #pragma unroll
            for (int p = 0; p < 4; p++) {
                float lo, hi; unpack2(cb2[p], lo, hi);
                cb_s[((2*p)*64 + chl)*32 + lane]   = lo;
                cb_s[((2*p+1)*64 + chl)*32 + lane] = hi;
            }
        }
        __syncthreads();

        // phase C: warp = head e; acc += Wv'^T @ cbar_e
        {
            const float* wvp = g_wv + ((size_t)warp*HIDDEN + cbk*64)*HDIM + dg*8;
            const float* cbb = cb_s + (warp*64)*32 + pg*8;
            #pragma unroll 4
            for (int ch = 0; ch < 64; ch++) {
                float4 w0 = *(const float4*)(wvp + (size_t)ch*HDIM);
                float4 w1 = *(const float4*)(wvp + (size_t)ch*HDIM + 4);
                ulonglong2 c01 = *(const ulonglong2*)(cbb + ch*32);
                ulonglong2 c23 = *(const ulonglong2*)(cbb + ch*32 + 4);
                ull bb0 = c01.x, bb1 = c01.y, bb2 = c23.x, bb3 = c23.y;
                ull as[8] = {splat2(w0.x), splat2(w0.y), splat2(w0.z), splat2(w0.w),
                             splat2(w1.x), splat2(w1.y), splat2(w1.z), splat2(w1.w)};
                #pragma unroll
                for (int i = 0; i < 8; i++) {
                    ffma2(acc2[i][0], as[i], bb0);
                    ffma2(acc2[i][1], as[i], bb1);
                    ffma2(acc2[i][2], as[i], bb2);
                    ffma2(acc2[i][3], as[i], bb3);
                }
            }
        }
        __syncthreads();
    }

    // ---- stage H[512][32] into smem (overlay on cb_s) ----
    #pragma unroll
    for (int i = 0; i < 8; i++) {
        float r[8];
        #pragma unroll
        for (int j = 0; j < 4; j++) unpack2(acc2[i][j], r[2*j], r[2*j+1]);
        float* dst = hs + (warp*HDIM + dg*8 + i)*32 + pg*8;
        *(float4*)(dst)     = make_float4(r[0], r[1], r[2], r[3]);
        *(float4*)(dst + 4) = make_float4(r[4], r[5], r[6], r[7]);
    }
    __syncthreads();

    // ---- fused out-GEMM: out[256co][32px] = W_out^T @ H + b_out ----
    // thread: co = warp*32 + cg*8 + {0..7} (4 co-pairs), px = pxg*4 + {0..3} (splats)
    int cg = lane >> 3, pxg = lane & 7;
    int coL = warp*32 + cg*8;
    ull oacc[4][4];
    #pragma unroll
    for (int i = 0; i < 4; i++)
        #pragma unroll
        for (int j = 0; j < 4; j++) oacc[i][j] = 0ull;

    const float4* wf4 = (const float4*)w_out;
    for (int kc = 0; kc < HS; kc += 32) {
        // stage w_out chunk [32k][256co] = 32KB contiguous copy
        #pragma unroll
        for (int i = 0; i < 8; i++)
            ((float4*)sW)[tid + i*256] = wf4[kc*64 + tid + i*256];
        __syncthreads();
        #pragma unroll 8
        for (int k = 0; k < 32; k++) {
            ulonglong2 a01 = *(const ulonglong2*)&sW[k*256 + coL];
            ulonglong2 a23 = *(const ulonglong2*)&sW[k*256 + coL + 4];
            float4 bv = *(const float4*)&hs[(kc + k)*32 + pxg*4];
            ull b0 = splat2(bv.x), b1 = splat2(bv.y), b2 = splat2(bv.z), b3 = splat2(bv.w);
            ull aa[4] = {a01.x, a01.y, a23.x, a23.y};
            #pragma unroll
            for (int i = 0; i < 4; i++) {
                ffma2(oacc[i][0], aa[i], b0);
                ffma2(oacc[i][1], aa[i], b1);
                ffma2(oacc[i][2], aa[i], b2);
                ffma2(oacc[i][3], aa[i], b3);
            }
        }
        __syncthreads();
    }

    // epilogue: out[b][co][h][w], px = w
    #pragma unroll
    for (int i = 0; i < 4; i++) {
        float lo[4], hi[4];
        #pragma unroll
        for (int j = 0; j < 4; j++) unpack2(oacc[i][j], lo[j], hi[j]);
        int co = coL + 2*i;
        float bl = b_out[co], bh = b_out[co+1];
        float* d0 = out + ((size_t)(b*HIDDEN + co))*PIXB + h*WW + pxg*4;
        float* d1 = d0 + PIXB;
        *(float4*)d0 = make_float4(lo[0]+bl, lo[1]+bl, lo[2]+bl, lo[3]+bl);
        *(float4*)d1 = make_float4(hi[0]+bh, hi[1]+bh, hi[2]+bh, hi[3]+bh);
    }
}

// ---------------- launch ----------------
extern "C" void kernel_launch(void* const* d_in, const int* in_sizes, int n_in,
                              void* d_out, int out_size)
{
    const int*   q     = (const int*)  d_in[0];
    const float* c     = (const float*)d_in[1];
    const float* rms_w = (const float*)d_in[2];
    const float* emb   = (const float*)d_in[3];
    const float* w1    = (const float*)d_in[4];
    const float* b1    = (const float*)d_in[5];
    const float* w2    = (const float*)d_in[6];
    const float* b2    = (const float*)d_in[7];
    const float* w_kv  = (const float*)d_in[8];
    const float* w_out = (const float*)d_in[9];
    const float* b_out = (const float*)d_in[10];
    float* out = (float*)d_out;

    const int ATTN_SMEM = 99328;   // bytes
    cudaFuncSetAttribute(k_attn3, cudaFuncAttributeMaxDynamicSharedMemorySize, ATTN_SMEM);

    k_qh   <<<BATCH, 512>>>(q, emb, w1, b1, w2, b2);
    k_prep2<<<HIDDEN + NHEADS*BATCH, 512>>>(w_kv, rms_w);
    k_attn3<<<BATCH*HH, 256, ATTN_SMEM>>>(c, w_out, b_out, out);
}

// round 7
// speedup vs baseline: 1.9582x; 1.1017x over previous
#include <cuda_runtime.h>
#include <cuda_bf16.h>
#include <math.h>

#define HIDDEN 256
#define HS     512
#define NHEADS 8
#define HDIM   64
#define NTOK   8
#define BATCH  8
#define HH     32
#define WW     32
#define PIXB   (HH*WW)        // 1024 pixels per batch
#define NPIX   (BATCH*PIXB)   // 8192
#define EPSV   1e-6f
#define ATTN_SCALE 0.125f     // 64^-0.5

typedef unsigned long long ull;

// ---- packed f32x2 helpers (FFMA2: ptxas never emits this from C++) ----
__device__ __forceinline__ ull pack2(float lo, float hi) {
    ull r; asm("mov.b64 %0, {%1, %2};" : "=l"(r) : "f"(lo), "f"(hi)); return r;
}
__device__ __forceinline__ ull splat2(float x) {
    ull r; asm("mov.b64 %0, {%1, %1};" : "=l"(r) : "f"(x)); return r;
}
__device__ __forceinline__ void unpack2(ull p, float& lo, float& hi) {
    asm("mov.b64 {%0, %1}, %2;" : "=f"(lo), "=f"(hi) : "l"(p));
}
__device__ __forceinline__ void ffma2(ull& d, ull a, ull b) {
    asm("fma.rn.f32x2 %0, %1, %2, %0;" : "+l"(d) : "l"(a), "l"(b));
}

// ---------------- device scratch ----------------
__device__ float g_t[BATCH*HS];                  // silu(qe@w1+b1)
__device__ float g_wqc[BATCH*NHEADS*HIDDEN];     // [b][e][256]  (scale & rms_w folded)
__device__ float g_wv[NHEADS*HIDDEN*HDIM];       // [e][ch][d]   (rms_w folded V weights)

// ---------------- K0: g_wv repack (blocks 0..255)  ||  MLP layer 1 (blocks 256..319) ----------------
__global__ __launch_bounds__(256) void k_front(
    const float* __restrict__ w_kv, const float* __restrict__ rms_w,
    const int* __restrict__ q, const float* __restrict__ emb,
    const float* __restrict__ w1, const float* __restrict__ b1)
{
    __shared__ float qe[HIDDEN];
    __shared__ float part[4][64];
    int tid = threadIdx.x;

    if (blockIdx.x < HIDDEN) {
        int ch = blockIdx.x;
        float rw = rms_w[ch];
        #pragma unroll
        for (int i = 0; i < 2; i++) {
            int idx = tid + i*256;
            int e = idx >> 6, d = idx & 63;
            g_wv[((size_t)e*HIDDEN + ch)*HDIM + d] =
                rw * w_kv[(size_t)ch*(2*HS) + e*(2*HDIM) + HDIM + d];
        }
        return;
    }

    // MLP layer 1: t[b][c0+col] = silu(qe @ w1[:, c0+col] + b1)
    int idx = blockIdx.x - HIDDEN;       // 0..63
    int b  = idx >> 3;
    int c0 = (idx & 7) * 64;
    qe[tid] = emb[q[b]*HIDDEN + tid];
    __syncthreads();

    int col = tid & 63, ks = tid >> 6;   // 4-way k-split, 64 ch each
    float acc = 0.f;
    #pragma unroll 1
    for (int u0 = 0; u0 < 64; u0 += 16) {
        float v[16];
        #pragma unroll
        for (int u = 0; u < 16; u++)
            v[u] = w1[(size_t)(ks*64 + u0 + u)*HS + c0 + col];
        #pragma unroll
        for (int u = 0; u < 16; u++)
            acc = fmaf(qe[ks*64 + u0 + u], v[u], acc);
    }
    part[ks][col] = acc;
    __syncthreads();
    if (tid < 64) {
        float s = part[0][tid] + part[1][tid] + part[2][tid] + part[3][tid] + b1[c0 + tid];
        g_t[b*HS + c0 + tid] = s / (1.f + expf(-s));
    }
}

// ---------------- K1: fused MLP layer 2 (one head's 64 outputs) + wqc ----------------
// Block = (b, e). Phase 1: qh[e*64+d] = t @ w2[:, e*64+d] + b2 (split-K x4).
// Phase 2: wqc[b][e][ch] = ATTN_SCALE * rms_w[ch] * sum_d qh_d * w_kv[ch][e*128+d]
__global__ __launch_bounds__(256) void k_mid(
    const float* __restrict__ w2, const float* __restrict__ b2,
    const float* __restrict__ w_kv, const float* __restrict__ rms_w)
{
    __shared__ float t_s[HS];
    __shared__ float part[4][64];
    __shared__ float qh_s[HDIM];
    int tid = threadIdx.x;
    int b = blockIdx.x >> 3, e = blockIdx.x & 7;

    t_s[tid]       = g_t[b*HS + tid];
    t_s[tid + 256] = g_t[b*HS + tid + 256];
    __syncthreads();

    int d = tid & 63, ks = tid >> 6;     // 4-way k-split, 128 k each
    float acc = 0.f;
    #pragma unroll 1
    for (int u0 = 0; u0 < 128; u0 += 16) {
        float v[16];
        #pragma unroll
        for (int u = 0; u < 16; u++)
            v[u] = w2[(size_t)(ks*128 + u0 + u)*HS + e*HDIM + d];
        #pragma unroll
        for (int u = 0; u < 16; u++)
            acc = fmaf(t_s[ks*128 + u0 + u], v[u], acc);
    }
    part[ks][d] = acc;
    __syncthreads();
    if (tid < 64)
        qh_s[tid] = part[0][tid] + part[1][tid] + part[2][tid] + part[3][tid] + b2[e*HDIM + tid];
    __syncthreads();

    // phase 2: one thread per channel
    {
        int ch = tid;
        const float4* wk = (const float4*)(w_kv + (size_t)ch*(2*HS) + e*(2*HDIM));
        float s = 0.f;
        #pragma unroll
        for (int d4 = 0; d4 < HDIM/4; d4++) {
            float4 w = wk[d4];
            s = fmaf(qh_s[d4*4+0], w.x, s);
            s = fmaf(qh_s[d4*4+1], w.y, s);
            s = fmaf(qh_s[d4*4+2], w.z, s);
            s = fmaf(qh_s[d4*4+3], w.w, s);
        }
        g_wqc[(b*NHEADS + e)*HIDDEN + ch] = s * rms_w[ch] * ATTN_SCALE;
    }
}

// ---------------- K2: FULLY FUSED: rmsnorm + dots + softmax + cbar + V-GEMM + out-GEMM ----------------
// Block = one (b,h) row of 32 pixels, 256 threads (8 warps). smem 99328 B.
__global__ __launch_bounds__(256, 2) void k_attn3(
    const float* __restrict__ c,
    const float* __restrict__ w_out, const float* __restrict__ b_out,
    float* __restrict__ out)
{
    extern __shared__ ull smu[];
    ull*   swq2  = smu;              // [ch][4 head-pairs]
    ull*   a2_s  = smu + 1024;       // [n][4 head-pairs][lane]
    float* fb    = (float*)(smu + 2048);
    float* s_s   = fb;               // dots [e][n][p]
    float* rms_s = fb + 2048;        // [n][p]
    float* a_s   = fb + 2304;        // attn*inv_rms [e][n][p]
    float* cb_s  = fb + 4352;        // cbar chunk [e][64ch][32p]
    float* sW    = (float*)smu;      // overlay: w_out chunk [32k][256co]
    float* hs    = cb_s;             // overlay: H [512d][32px]

    int b = blockIdx.x >> 5;
    int h = blockIdx.x & 31;
    int tid = threadIdx.x;
    int warp = tid >> 5, lane = tid & 31;

    for (int i = tid; i < HIDDEN*4; i += 256) {
        int ch = i >> 2, p = i & 3;
        float lo = g_wqc[b*NHEADS*HIDDEN + (2*p)*HIDDEN + ch];
        float hi = g_wqc[b*NHEADS*HIDDEN + (2*p+1)*HIDDEN + ch];
        swq2[i] = pack2(lo, hi);
    }
    __syncthreads();

    // ---- pass A: sumsq + dots (warp = token n, lane = pixel p), MLP=16 ----
    {
        const float* cp = c + ((size_t)(b*NTOK + warp)*HIDDEN)*PIXB + h*WW + lane;
        float ss = 0.f;
        ull sd2[4] = {0ull, 0ull, 0ull, 0ull};
        #pragma unroll 1
        for (int ch0 = 0; ch0 < HIDDEN; ch0 += 16) {
            float v[16];
            #pragma unroll
            for (int u = 0; u < 16; u++) v[u] = cp[(size_t)(ch0+u)*PIXB];
            #pragma unroll
            for (int u = 0; u < 16; u++) {
                int ch = ch0 + u;
                ss = fmaf(v[u], v[u], ss);
                ull v2 = splat2(v[u]);
                ulonglong2 s01 = *(const ulonglong2*)(swq2 + ch*4);
                ulonglong2 s23 = *(const ulonglong2*)(swq2 + ch*4 + 2);
                ffma2(sd2[0], v2, s01.x);
                ffma2(sd2[1], v2, s01.y);
                ffma2(sd2[2], v2, s23.x);
                ffma2(sd2[3], v2, s23.y);
            }
        }
        rms_s[warp*32 + lane] = rsqrtf(ss*(1.0f/HIDDEN) + EPSV);
        #pragma unroll
        for (int p = 0; p < 4; p++) {
            float lo, hi; unpack2(sd2[p], lo, hi);
            s_s[((2*p)*NTOK + warp)*32 + lane]   = lo;
            s_s[((2*p+1)*NTOK + warp)*32 + lane] = hi;
        }
    }
    __syncthreads();

    // ---- softmax ----
    {
        int e = tid >> 5, p = tid & 31;
        float d[NTOK], m = -1e30f;
        #pragma unroll
        for (int n = 0; n < NTOK; n++) {
            d[n] = s_s[(e*NTOK + n)*32 + p] * rms_s[n*32 + p];
            m = fmaxf(m, d[n]);
        }
        float sum = 0.f;
        #pragma unroll
        for (int n = 0; n < NTOK; n++) { d[n] = expf(d[n] - m); sum += d[n]; }
        float inv = 1.f / sum;
        #pragma unroll
        for (int n = 0; n < NTOK; n++)
            a_s[(e*NTOK + n)*32 + p] = d[n] * inv * rms_s[n*32 + p];
    }
    __syncthreads();

    for (int i = tid; i < 1024; i += 256) {
        int n = i >> 7, p = (i >> 5) & 3, l2 = i & 31;
        float lo = a_s[((2*p)*NTOK + n)*32 + l2];
        float hi = a_s[((2*p+1)*NTOK + n)*32 + l2];
        a2_s[i] = pack2(lo, hi);
    }
    __syncthreads();

    // ---- chunked cbar + per-head V-GEMM ----
    int dg = lane >> 2, pg = lane & 3;
    ull acc2[8][4];
    #pragma unroll
    for (int i = 0; i < 8; i++)
        #pragma unroll
        for (int j = 0; j < 4; j++) acc2[i][j] = 0ull;

    for (int cbk = 0; cbk < 4; cbk++) {
        #pragma unroll
        for (int cc = 0; cc < 8; cc++) {
            int chl = warp*8 + cc;
            int ch  = cbk*64 + chl;
            const float* cp = c + ((size_t)(b*NTOK)*HIDDEN + ch)*PIXB + h*WW + lane;
            float v[NTOK];
            #pragma unroll
            for (int n = 0; n < NTOK; n++) v[n] = cp[(size_t)n*HIDDEN*PIXB];
            ull cb2[4] = {0ull, 0ull, 0ull, 0ull};
            #pragma unroll
            for (int n = 0; n < NTOK; n++) {
                ull v2 = splat2(v[n]);
                ffma2(cb2[0], v2, a2_s[(n*4 + 0)*32 + lane]);
                ffma2(cb2[1], v2, a2_s[(n*4 + 1)*32 + lane]);
                ffma2(cb2[2], v2, a2_s[(n*4 + 2)*32 + lane]);
                ffma2(cb2[3], v2, a2_s[(n*4 + 3)*32 + lane]);
            }
            #pragma unroll
            for (int p = 0; p < 4; p++) {
                float lo, hi; unpack2(cb2[p], lo, hi);
                cb_s[((2*p)*64 + chl)*32 + lane]   = lo;
                cb_s[((2*p+1)*64 + chl)*32 + lane] = hi;
            }
        }
        __syncthreads();

        {
            const float* wvp = g_wv + ((size_t)warp*HIDDEN + cbk*64)*HDIM + dg*8;
            const float* cbb = cb_s + (warp*64)*32 + pg*8;
            #pragma unroll 4
            for (int ch = 0; ch < 64; ch++) {
                float4 w0 = *(const float4*)(wvp + (size_t)ch*HDIM);
                float4 w1v = *(const float4*)(wvp + (size_t)ch*HDIM + 4);
                ulonglong2 c01 = *(const ulonglong2*)(cbb + ch*32);
                ulonglong2 c23 = *(const ulonglong2*)(cbb + ch*32 + 4);
                ull bb0 = c01.x, bb1 = c01.y, bb2 = c23.x, bb3 = c23.y;
                ull as[8] = {splat2(w0.x), splat2(w0.y), splat2(w0.z), splat2(w0.w),
                             splat2(w1v.x), splat2(w1v.y), splat2(w1v.z), splat2(w1v.w)};
                #pragma unroll
                for (int i = 0; i < 8; i++) {
                    ffma2(acc2[i][0], as[i], bb0);
                    ffma2(acc2[i][1], as[i], bb1);
                    ffma2(acc2[i][2], as[i], bb2);
                    ffma2(acc2[i][3], as[i], bb3);
                }
            }
        }
        __syncthreads();
    }

    // ---- stage H[512][32] into smem ----
    #pragma unroll
    for (int i = 0; i < 8; i++) {
        float r[8];
        #pragma unroll
        for (int j = 0; j < 4; j++) unpack2(acc2[i][j], r[2*j], r[2*j+1]);
        float* dst = hs + (warp*HDIM + dg*8 + i)*32 + pg*8;
        *(float4*)(dst)     = make_float4(r[0], r[1], r[2], r[3]);
        *(float4*)(dst + 4) = make_float4(r[4], r[5], r[6], r[7]);
    }
    __syncthreads();

    // ---- fused out-GEMM ----
    int cg = lane >> 3, pxg = lane & 7;
    int coL = warp*32 + cg*8;
    ull oacc[4][4];
    #pragma unroll
    for (int i = 0; i < 4; i++)
        #pragma unroll
        for (int j = 0; j < 4; j++) oacc[i][j] = 0ull;

    const float4* wf4 = (const float4*)w_out;
    for (int kc = 0; kc < HS; kc += 32) {
        #pragma unroll
        for (int i = 0; i < 8; i++)
            ((float4*)sW)[tid + i*256] = wf4[kc*64 + tid + i*256];
        __syncthreads();
        #pragma unroll 8
        for (int k = 0; k < 32; k++) {
            ulonglong2 a01 = *(const ulonglong2*)&sW[k*256 + coL];
            ulonglong2 a23 = *(const ulonglong2*)&sW[k*256 + coL + 4];
            float4 bv = *(const float4*)&hs[(kc + k)*32 + pxg*4];
            ull b0 = splat2(bv.x), b1v = splat2(bv.y), b2v = splat2(bv.z), b3 = splat2(bv.w);
            ull aa[4] = {a01.x, a01.y, a23.x, a23.y};
            #pragma unroll
            for (int i = 0; i < 4; i++) {
                ffma2(oacc[i][0], aa[i], b0);
                ffma2(oacc[i][1], aa[i], b1v);
                ffma2(oacc[i][2], aa[i], b2v);
                ffma2(oacc[i][3], aa[i], b3);
            }
        }
        __syncthreads();
    }

    #pragma unroll
    for (int i = 0; i < 4; i++) {
        float lo[4], hi[4];
        #pragma unroll
        for (int j = 0; j < 4; j++) unpack2(oacc[i][j], lo[j], hi[j]);
        int co = coL + 2*i;
        float bl = b_out[co], bh = b_out[co+1];
        float* d0 = out + ((size_t)(b*HIDDEN + co))*PIXB + h*WW + pxg*4;
        float* d1 = d0 + PIXB;
        *(float4*)d0 = make_float4(lo[0]+bl, lo[1]+bl, lo[2]+bl, lo[3]+bl);
        *(float4*)d1 = make_float4(hi[0]+bh, hi[1]+bh, hi[2]+bh, hi[3]+bh);
    }
}

// ---------------- launch ----------------
extern "C" void kernel_launch(void* const* d_in, const int* in_sizes, int n_in,
                              void* d_out, int out_size)
{
    const int*   q     = (const int*)  d_in[0];
    const float* c     = (const float*)d_in[1];
    const float* rms_w = (const float*)d_in[2];
    const float* emb   = (const float*)d_in[3];
    const float* w1    = (const float*)d_in[4];
    const float* b1    = (const float*)d_in[5];
    const float* w2    = (const float*)d_in[6];
    const float* b2    = (const float*)d_in[7];
    const float* w_kv  = (const float*)d_in[8];
    const float* w_out = (const float*)d_in[9];
    const float* b_out = (const float*)d_in[10];
    float* out = (float*)d_out;

    const int ATTN_SMEM = 99328;   // bytes
    cudaFuncSetAttribute(k_attn3, cudaFuncAttributeMaxDynamicSharedMemorySize, ATTN_SMEM);

    k_front<<<HIDDEN + 64, 256>>>(w_kv, rms_w, q, emb, w1, b1);
    k_mid  <<<BATCH*NHEADS, 256>>>(w2, b2, w_kv, rms_w);
    k_attn3<<<BATCH*HH, 256, ATTN_SMEM>>>(c, w_out, b_out, out);
}

// round 8
// speedup vs baseline: 2.3039x; 1.1765x over previous
#include <cuda_runtime.h>
#include <cuda_bf16.h>
#include <math.h>

#define HIDDEN 256
#define HS     512
#define NHEADS 8
#define HDIM   64
#define NTOK   8
#define BATCH  8
#define HH     32
#define WW     32
#define PIXB   (HH*WW)        // 1024 pixels per batch
#define NPIX   (BATCH*PIXB)   // 8192
#define EPSV   1e-6f
#define ATTN_SCALE 0.125f     // 64^-0.5

typedef unsigned long long ull;
typedef unsigned int uint32;

// ---- packed f32x2 helpers (FFMA2) ----
__device__ __forceinline__ ull pack2(float lo, float hi) {
    ull r; asm("mov.b64 %0, {%1, %2};" : "=l"(r) : "f"(lo), "f"(hi)); return r;
}
__device__ __forceinline__ ull splat2(float x) {
    ull r; asm("mov.b64 %0, {%1, %1};" : "=l"(r) : "f"(x)); return r;
}
__device__ __forceinline__ void unpack2(ull p, float& lo, float& hi) {
    asm("mov.b64 {%0, %1}, %2;" : "=f"(lo), "=f"(hi) : "l"(p));
}
__device__ __forceinline__ void ffma2(ull& d, ull a, ull b) {
    asm("fma.rn.f32x2 %0, %1, %2, %0;" : "+l"(d) : "l"(a), "l"(b));
}

// ---- tf32 mma helpers ----
__device__ __forceinline__ uint32 cvt_tf32(float x) {
    uint32 r; asm("cvt.rna.tf32.f32 %0, %1;" : "=r"(r) : "f"(x)); return r;
}
__device__ __forceinline__ void mma_tf32(float* d, const uint32* a, const uint32* b) {
    asm volatile("mma.sync.aligned.m16n8k8.row.col.f32.tf32.tf32.f32 "
        "{%0,%1,%2,%3}, {%4,%5,%6,%7}, {%8,%9}, {%0,%1,%2,%3};"
        : "+f"(d[0]), "+f"(d[1]), "+f"(d[2]), "+f"(d[3])
        : "r"(a[0]), "r"(a[1]), "r"(a[2]), "r"(a[3]), "r"(b[0]), "r"(b[1]));
}

// ---------------- device scratch ----------------
__device__ float g_t[BATCH*HS];                  // silu(qe@w1+b1)
__device__ float g_wqc[BATCH*NHEADS*HIDDEN];     // [b][e][256]  (scale & rms_w folded)
__device__ float g_wv[NHEADS*HIDDEN*HDIM];       // [e][ch][d]   (rms_w folded V weights)

// ---------------- K0: g_wv repack (blocks 0..255) || MLP layer 1 (blocks 256..319) ----------------
__global__ __launch_bounds__(256) void k_front(
    const float* __restrict__ w_kv, const float* __restrict__ rms_w,
    const int* __restrict__ q, const float* __restrict__ emb,
    const float* __restrict__ w1, const float* __restrict__ b1)
{
    __shared__ float qe[HIDDEN];
    __shared__ float part[4][64];
    int tid = threadIdx.x;

    if (blockIdx.x < HIDDEN) {
        int ch = blockIdx.x;
        float rw = rms_w[ch];
        #pragma unroll
        for (int i = 0; i < 2; i++) {
            int idx = tid + i*256;
            int e = idx >> 6, d = idx & 63;
            g_wv[((size_t)e*HIDDEN + ch)*HDIM + d] =
                rw * w_kv[(size_t)ch*(2*HS) + e*(2*HDIM) + HDIM + d];
        }
        return;
    }

    int idx = blockIdx.x - HIDDEN;       // 0..63
    int b  = idx >> 3;
    int c0 = (idx & 7) * 64;
    qe[tid] = emb[q[b]*HIDDEN + tid];
    __syncthreads();

    int col = tid & 63, ks = tid >> 6;
    float acc = 0.f;
    #pragma unroll 1
    for (int u0 = 0; u0 < 64; u0 += 16) {
        float v[16];
        #pragma unroll
        for (int u = 0; u < 16; u++)
            v[u] = w1[(size_t)(ks*64 + u0 + u)*HS + c0 + col];
        #pragma unroll
        for (int u = 0; u < 16; u++)
            acc = fmaf(qe[ks*64 + u0 + u], v[u], acc);
    }
    part[ks][col] = acc;
    __syncthreads();
    if (tid < 64) {
        float s = part[0][tid] + part[1][tid] + part[2][tid] + part[3][tid] + b1[c0 + tid];
        g_t[b*HS + c0 + tid] = s / (1.f + expf(-s));
    }
}

// ---------------- K1: fused MLP layer 2 + wqc ----------------
__global__ __launch_bounds__(256) void k_mid(
    const float* __restrict__ w2, const float* __restrict__ b2,
    const float* __restrict__ w_kv, const float* __restrict__ rms_w)
{
    __shared__ float t_s[HS];
    __shared__ float part[4][64];
    __shared__ float qh_s[HDIM];
    int tid = threadIdx.x;
    int b = blockIdx.x >> 3, e = blockIdx.x & 7;

    t_s[tid]       = g_t[b*HS + tid];
    t_s[tid + 256] = g_t[b*HS + tid + 256];
    __syncthreads();

    int d = tid & 63, ks = tid >> 6;
    float acc = 0.f;
    #pragma unroll 1
    for (int u0 = 0; u0 < 128; u0 += 16) {
        float v[16];
        #pragma unroll
        for (int u = 0; u < 16; u++)
            v[u] = w2[(size_t)(ks*128 + u0 + u)*HS + e*HDIM + d];
        #pragma unroll
        for (int u = 0; u < 16; u++)
            acc = fmaf(t_s[ks*128 + u0 + u], v[u], acc);
    }
    part[ks][d] = acc;
    __syncthreads();
    if (tid < 64)
        qh_s[tid] = part[0][tid] + part[1][tid] + part[2][tid] + part[3][tid] + b2[e*HDIM + tid];
    __syncthreads();

    {
        int ch = tid;
        const float4* wk = (const float4*)(w_kv + (size_t)ch*(2*HS) + e*(2*HDIM));
        float s = 0.f;
        #pragma unroll
        for (int d4 = 0; d4 < HDIM/4; d4++) {
            float4 w = wk[d4];
            s = fmaf(qh_s[d4*4+0], w.x, s);
            s = fmaf(qh_s[d4*4+1], w.y, s);
            s = fmaf(qh_s[d4*4+2], w.z, s);
            s = fmaf(qh_s[d4*4+3], w.w, s);
        }
        g_wqc[(b*NHEADS + e)*HIDDEN + ch] = s * rms_w[ch] * ATTN_SCALE;
    }
}

// ---------------- K2: FULLY FUSED kernel ----------------
// Block = one (b,h) row of 32 pixels, 256 threads (8 warps).
// smem (100352 B):
//   region P (33792 B): swq2 ull[1024] | a2_s ull[1024] | s_s f[2048] | rms f[256] | a_s f[2048]
//        -> overlay after phase C: sW uint[32k][264co] (tf32) = 33792 B exactly
//   region Q (66560 B): cb_s f[8e*64ch*32p] (65536 B)
//        -> overlay after phase C: hst uint[32px][520k] (tf32) = 66560 B
__global__ __launch_bounds__(256, 2) void k_attn3(
    const float* __restrict__ c,
    const float* __restrict__ w_out, const float* __restrict__ b_out,
    float* __restrict__ out)
{
    extern __shared__ ull smu[];
    ull*   swq2  = smu;              // [ch][4 head-pairs]
    ull*   a2_s  = smu + 1024;       // [n][4 head-pairs][lane]
    float* fb    = (float*)(smu + 2048);
    float* s_s   = fb;               // dots [e][n][p]
    float* rms_s = fb + 2048;        // [n][p]
    float* a_s   = fb + 2304;        // attn*inv_rms [e][n][p]
    float* cb_s  = fb + 4352;        // cbar chunk [e][64ch][32p]
    uint32* sW   = (uint32*)smu;                      // overlay: tf32 w_out chunk [32][264]
    uint32* hst  = (uint32*)((char*)smu + 33792);     // overlay: tf32 H [32px][520]

    int b = blockIdx.x >> 5;
    int h = blockIdx.x & 31;
    int tid = threadIdx.x;
    int warp = tid >> 5, lane = tid & 31;

    for (int i = tid; i < HIDDEN*4; i += 256) {
        int ch = i >> 2, p = i & 3;
        float lo = g_wqc[b*NHEADS*HIDDEN + (2*p)*HIDDEN + ch];
        float hi = g_wqc[b*NHEADS*HIDDEN + (2*p+1)*HIDDEN + ch];
        swq2[i] = pack2(lo, hi);
    }
    __syncthreads();

    // ---- pass A: sumsq + dots (warp = token n, lane = pixel p), MLP=16 ----
    {
        const float* cp = c + ((size_t)(b*NTOK + warp)*HIDDEN)*PIXB + h*WW + lane;
        float ss = 0.f;
        ull sd2[4] = {0ull, 0ull, 0ull, 0ull};
        #pragma unroll 1
        for (int ch0 = 0; ch0 < HIDDEN; ch0 += 16) {
            float v[16];
            #pragma unroll
            for (int u = 0; u < 16; u++) v[u] = cp[(size_t)(ch0+u)*PIXB];
            #pragma unroll
            for (int u = 0; u < 16; u++) {
                int ch = ch0 + u;
                ss = fmaf(v[u], v[u], ss);
                ull v2 = splat2(v[u]);
                ulonglong2 s01 = *(const ulonglong2*)(swq2 + ch*4);
                ulonglong2 s23 = *(const ulonglong2*)(swq2 + ch*4 + 2);
                ffma2(sd2[0], v2, s01.x);
                ffma2(sd2[1], v2, s01.y);
                ffma2(sd2[2], v2, s23.x);
                ffma2(sd2[3], v2, s23.y);
            }
        }
        rms_s[warp*32 + lane] = rsqrtf(ss*(1.0f/HIDDEN) + EPSV);
        #pragma unroll
        for (int p = 0; p < 4; p++) {
            float lo, hi; unpack2(sd2[p], lo, hi);
            s_s[((2*p)*NTOK + warp)*32 + lane]   = lo;
            s_s[((2*p+1)*NTOK + warp)*32 + lane] = hi;
        }
    }
    __syncthreads();

    // ---- softmax ----
    {
        int e = tid >> 5, p = tid & 31;
        float d[NTOK], m = -1e30f;
        #pragma unroll
        for (int n = 0; n < NTOK; n++) {
            d[n] = s_s[(e*NTOK + n)*32 + p] * rms_s[n*32 + p];
            m = fmaxf(m, d[n]);
        }
        float sum = 0.f;
        #pragma unroll
        for (int n = 0; n < NTOK; n++) { d[n] = expf(d[n] - m); sum += d[n]; }
        float inv = 1.f / sum;
        #pragma unroll
        for (int n = 0; n < NTOK; n++)
            a_s[(e*NTOK + n)*32 + p] = d[n] * inv * rms_s[n*32 + p];
    }
    __syncthreads();

    for (int i = tid; i < 1024; i += 256) {
        int n = i >> 7, p = (i >> 5) & 3, l2 = i & 31;
        float lo = a_s[((2*p)*NTOK + n)*32 + l2];
        float hi = a_s[((2*p+1)*NTOK + n)*32 + l2];
        a2_s[i] = pack2(lo, hi);
    }
    __syncthreads();

    // ---- chunked cbar + per-head V-GEMM (FFMA2) ----
    int dg = lane >> 2, pg = lane & 3;
    ull acc2[8][4];
    #pragma unroll
    for (int i = 0; i < 8; i++)
        #pragma unroll
        for (int j = 0; j < 4; j++) acc2[i][j] = 0ull;

    for (int cbk = 0; cbk < 4; cbk++) {
        #pragma unroll
        for (int cc = 0; cc < 8; cc++) {
            int chl = warp*8 + cc;
            int ch  = cbk*64 + chl;
            const float* cp = c + ((size_t)(b*NTOK)*HIDDEN + ch)*PIXB + h*WW + lane;
            float v[NTOK];
            #pragma unroll
            for (int n = 0; n < NTOK; n++) v[n] = cp[(size_t)n*HIDDEN*PIXB];
            ull cb2[4] = {0ull, 0ull, 0ull, 0ull};
            #pragma unroll
            for (int n = 0; n < NTOK; n++) {
                ull v2 = splat2(v[n]);
                ffma2(cb2[0], v2, a2_s[(n*4 + 0)*32 + lane]);
                ffma2(cb2[1], v2, a2_s[(n*4 + 1)*32 + lane]);
                ffma2(cb2[2], v2, a2_s[(n*4 + 2)*32 + lane]);
                ffma2(cb2[3], v2, a2_s[(n*4 + 3)*32 + lane]);
            }
            #pragma unroll
            for (int p = 0; p < 4; p++) {
                float lo, hi; unpack2(cb2[p], lo, hi);
                cb_s[((2*p)*64 + chl)*32 + lane]   = lo;
                cb_s[((2*p+1)*64 + chl)*32 + lane] = hi;
            }
        }
        __syncthreads();

        {
            const float* wvp = g_wv + ((size_t)warp*HIDDEN + cbk*64)*HDIM + dg*8;
            const float* cbb = cb_s + (warp*64)*32 + pg*8;
            #pragma unroll 4
            for (int ch = 0; ch < 64; ch++) {
                float4 w0 = *(const float4*)(wvp + (size_t)ch*HDIM);
                float4 w1v = *(const float4*)(wvp + (size_t)ch*HDIM + 4);
                ulonglong2 c01 = *(const ulonglong2*)(cbb + ch*32);
                ulonglong2 c23 = *(const ulonglong2*)(cbb + ch*32 + 4);
                ull bb0 = c01.x, bb1 = c01.y, bb2 = c23.x, bb3 = c23.y;
                ull as[8] = {splat2(w0.x), splat2(w0.y), splat2(w0.z), splat2(w0.w),
                             splat2(w1v.x), splat2(w1v.y), splat2(w1v.z), splat2(w1v.w)};
                #pragma unroll
                for (int i = 0; i < 8; i++) {
                    ffma2(acc2[i][0], as[i], bb0);
                    ffma2(acc2[i][1], as[i], bb1);
                    ffma2(acc2[i][2], as[i], bb2);
                    ffma2(acc2[i][3], as[i], bb3);
                }
            }
        }
        __syncthreads();
    }

    // ---- stage H as tf32 into hst[px][520 + k(d)] (overlay on cb_s) ----
    // thread owns d = warp*64 + dg*8 + {0..7}, px = pg*8 + {0..7}
    #pragma unroll
    for (int jj = 0; jj < 8; jj++) {
        int px = pg*8 + jj;
        uint32 t0[4], t1[4];
        #pragma unroll
        for (int i = 0; i < 8; i++) {
            float lo, hi; unpack2(acc2[i][jj >> 1], lo, hi);
            float v = (jj & 1) ? hi : lo;
            if (i < 4) t0[i] = cvt_tf32(v); else t1[i-4] = cvt_tf32(v);
        }
        uint32* dst = hst + px*520 + warp*HDIM + dg*8;
        *(uint4*)(dst)     = make_uint4(t0[0], t0[1], t0[2], t0[3]);
        *(uint4*)(dst + 4) = make_uint4(t1[0], t1[1], t1[2], t1[3]);
    }
    __syncthreads();

    // ---- out-GEMM via tf32 mma: out[co 32/warp][32px] = W_out^T @ H + bias ----
    // m16n8k8: A = w_out^T [co][k] row-major from sW[k][264], B = H [k][px] col-major from hst[px][520]
    int r4 = lane >> 2, c4 = lane & 3;
    float D[2][4][4];
    #pragma unroll
    for (int m = 0; m < 2; m++)
        #pragma unroll
        for (int n = 0; n < 4; n++)
            #pragma unroll
            for (int t = 0; t < 4; t++) D[m][n][t] = 0.f;

    const float4* wf4 = (const float4*)w_out;
    for (int kc = 0; kc < HS; kc += 32) {
        // stage w_out chunk [32k][256co] -> sW[k*264 + co] (tf32)
        #pragma unroll
        for (int i = 0; i < 8; i++) {
            int f4i = tid + i*256;
            int k = f4i >> 6, co4 = f4i & 63;
            float4 w = wf4[(size_t)(kc + k)*64 + co4];
            uint4 t;
            t.x = cvt_tf32(w.x); t.y = cvt_tf32(w.y);
            t.z = cvt_tf32(w.z); t.w = cvt_tf32(w.w);
            *(uint4*)&sW[k*264 + co4*4] = t;
        }
        __syncthreads();
        #pragma unroll
        for (int kt = 0; kt < 4; kt++) {
            int lk = kt*8;
            uint32 afr[2][4], bfr[4][2];
            #pragma unroll
            for (int m = 0; m < 2; m++) {
                int co = warp*32 + m*16 + r4;
                afr[m][0] = sW[(lk + c4)*264 + co];
                afr[m][1] = sW[(lk + c4)*264 + co + 8];
                afr[m][2] = sW[(lk + c4 + 4)*264 + co];
                afr[m][3] = sW[(lk + c4 + 4)*264 + co + 8];
            }
            #pragma unroll
            for (int n = 0; n < 4; n++) {
                int px = n*8 + r4;
                bfr[n][0] = hst[px*520 + kc + lk + c4];
                bfr[n][1] = hst[px*520 + kc + lk + c4 + 4];
            }
            #pragma unroll
            for (int m = 0; m < 2; m++)
                #pragma unroll
                for (int n = 0; n < 4; n++)
                    mma_tf32(D[m][n], afr[m], bfr[n]);
        }
        __syncthreads();
    }

    // epilogue: D c0:(r4, 2*c4) c1:(r4, 2*c4+1) c2/c3: row+8
    #pragma unroll
    for (int m = 0; m < 2; m++) {
        int co0 = warp*32 + m*16 + r4;
        float bl = b_out[co0], bh = b_out[co0 + 8];
        #pragma unroll
        for (int n = 0; n < 4; n++) {
            int px = n*8 + 2*c4;
            float* d0 = out + ((size_t)(b*HIDDEN + co0))*PIXB + h*WW + px;
            float* d1 = out + ((size_t)(b*HIDDEN + co0 + 8))*PIXB + h*WW + px;
            *(float2*)d0 = make_float2(D[m][n][0] + bl, D[m][n][1] + bl);
            *(float2*)d1 = make_float2(D[m][n][2] + bh, D[m][n][3] + bh);
        }
    }
}

// ---------------- launch ----------------
extern "C" void kernel_launch(void* const* d_in, const int* in_sizes, int n_in,
                              void* d_out, int out_size)
{
    const int*   q     = (const int*)  d_in[0];
    const float* c     = (const float*)d_in[1];
    const float* rms_w = (const float*)d_in[2];
    const float* emb   = (const float*)d_in[3];
    const float* w1    = (const float*)d_in[4];
    const float* b1    = (const float*)d_in[5];
    const float* w2    = (const float*)d_in[6];
    const float* b2    = (const float*)d_in[7];
    const float* w_kv  = (const float*)d_in[8];
    const float* w_out = (const float*)d_in[9];
    const float* b_out = (const float*)d_in[10];
    float* out = (float*)d_out;

    const int ATTN_SMEM = 33792 + 66560;   // 100352 B
    cudaFuncSetAttribute(k_attn3, cudaFuncAttributeMaxDynamicSharedMemorySize, ATTN_SMEM);

    k_front<<<HIDDEN + 64, 256>>>(w_kv, rms_w, q, emb, w1, b1);
    k_mid  <<<BATCH*NHEADS, 256>>>(w2, b2, w_kv, rms_w);
    k_attn3<<<BATCH*HH, 256, ATTN_SMEM>>>(c, w_out, b_out, out);
}

// round 9
// speedup vs baseline: 3.2529x; 1.4119x over previous
#include <cuda_runtime.h>
#include <cuda_bf16.h>
#include <math.h>

#define HIDDEN 256
#define HS     512
#define NHEADS 8
#define HDIM   64
#define NTOK   8
#define BATCH  8
#define HH     32
#define WW     32
#define PIXB   (HH*WW)        // 1024 pixels per batch
#define NPIX   (BATCH*PIXB)   // 8192
#define EPSV   1e-6f
#define ATTN_SCALE 0.125f     // 64^-0.5

typedef unsigned long long ull;
typedef unsigned int uint32;

// ---- packed f32x2 helpers (FFMA2) ----
__device__ __forceinline__ ull pack2(float lo, float hi) {
    ull r; asm("mov.b64 %0, {%1, %2};" : "=l"(r) : "f"(lo), "f"(hi)); return r;
}
__device__ __forceinline__ ull splat2(float x) {
    ull r; asm("mov.b64 %0, {%1, %1};" : "=l"(r) : "f"(x)); return r;
}
__device__ __forceinline__ void unpack2(ull p, float& lo, float& hi) {
    asm("mov.b64 {%0, %1}, %2;" : "=f"(lo), "=f"(hi) : "l"(p));
}
__device__ __forceinline__ void ffma2(ull& d, ull a, ull b) {
    asm("fma.rn.f32x2 %0, %1, %2, %0;" : "+l"(d) : "l"(a), "l"(b));
}

// ---- tf32 mma helpers ----
__device__ __forceinline__ uint32 cvt_tf32(float x) {
    uint32 r; asm("cvt.rna.tf32.f32 %0, %1;" : "=r"(r) : "f"(x)); return r;
}
__device__ __forceinline__ void mma_tf32(float* d, const uint32* a, const uint32* b) {
    asm volatile("mma.sync.aligned.m16n8k8.row.col.f32.tf32.tf32.f32 "
        "{%0,%1,%2,%3}, {%4,%5,%6,%7}, {%8,%9}, {%0,%1,%2,%3};"
        : "+f"(d[0]), "+f"(d[1]), "+f"(d[2]), "+f"(d[3])
        : "r"(a[0]), "r"(a[1]), "r"(a[2]), "r"(a[3]), "r"(b[0]), "r"(b[1]));
}

// ---------------- device scratch ----------------
__device__ float g_t[BATCH*HS];                  // silu(qe@w1+b1)
__device__ float g_wqc[BATCH*NHEADS*HIDDEN];     // [b][e][256]  (scale & rms_w folded)
// V weights as tf32 MMA A-fragments: [e][kk(32 k-steps)][m(4)][lane(32)] uint4
//   reg0=(d0+r4, ch0+c4) reg1=(d0+8+r4, ch0+c4) reg2=(d0+r4, ch0+c4+4) reg3=(d0+8+r4, ch0+c4+4)
__device__ uint4 g_wvt[NHEADS*32*4*32];

// ---------------- K0: wv fragment repack (blocks 0..127) || MLP layer 1 (blocks 128..191) ----------------
__global__ __launch_bounds__(256) void k_front(
    const float* __restrict__ w_kv, const float* __restrict__ rms_w,
    const int* __restrict__ q, const float* __restrict__ emb,
    const float* __restrict__ w1, const float* __restrict__ b1)
{
    __shared__ float qe[HIDDEN];
    __shared__ float part[4][64];
    int tid = threadIdx.x;

    if (blockIdx.x < 128) {
        int t = blockIdx.x*256 + tid;        // 0..32767
        int lane = t & 31, m = (t >> 5) & 3, kk = (t >> 7) & 31, e = t >> 12;
        int r4 = lane >> 2, c4 = lane & 3;
        int ch0 = kk*8 + c4, d0 = m*16 + r4;
        const float* base = w_kv + e*(2*HDIM) + HDIM;
        float rw0 = rms_w[ch0], rw4 = rms_w[ch0 + 4];
        uint4 o;
        o.x = cvt_tf32(rw0 * base[(size_t)ch0*(2*HS) + d0]);
        o.y = cvt_tf32(rw0 * base[(size_t)ch0*(2*HS) + d0 + 8]);
        o.z = cvt_tf32(rw4 * base[(size_t)(ch0+4)*(2*HS) + d0]);
        o.w = cvt_tf32(rw4 * base[(size_t)(ch0+4)*(2*HS) + d0 + 8]);
        g_wvt[t] = o;
        return;
    }

    int idx = blockIdx.x - 128;          // 0..63
    int b  = idx >> 3;
    int c0 = (idx & 7) * 64;
    qe[tid] = emb[q[b]*HIDDEN + tid];
    __syncthreads();

    int col = tid & 63, ks = tid >> 6;
    float acc = 0.f;
    #pragma unroll 1
    for (int u0 = 0; u0 < 64; u0 += 16) {
        float v[16];
        #pragma unroll
        for (int u = 0; u < 16; u++)
            v[u] = w1[(size_t)(ks*64 + u0 + u)*HS + c0 + col];
        #pragma unroll
        for (int u = 0; u < 16; u++)
            acc = fmaf(qe[ks*64 + u0 + u], v[u], acc);
    }
    part[ks][col] = acc;
    __syncthreads();
    if (tid < 64) {
        float s = part[0][tid] + part[1][tid] + part[2][tid] + part[3][tid] + b1[c0 + tid];
        g_t[b*HS + c0 + tid] = s / (1.f + expf(-s));
    }
}

// ---------------- K1: fused MLP layer 2 + wqc ----------------
__global__ __launch_bounds__(256) void k_mid(
    const float* __restrict__ w2, const float* __restrict__ b2,
    const float* __restrict__ w_kv, const float* __restrict__ rms_w)
{
    __shared__ float t_s[HS];
    __shared__ float part[4][64];
    __shared__ float qh_s[HDIM];
    int tid = threadIdx.x;
    int b = blockIdx.x >> 3, e = blockIdx.x & 7;

    t_s[tid]       = g_t[b*HS + tid];
    t_s[tid + 256] = g_t[b*HS + tid + 256];
    __syncthreads();

    int d = tid & 63, ks = tid >> 6;
    float acc = 0.f;
    #pragma unroll 1
    for (int u0 = 0; u0 < 128; u0 += 16) {
        float v[16];
        #pragma unroll
        for (int u = 0; u < 16; u++)
            v[u] = w2[(size_t)(ks*128 + u0 + u)*HS + e*HDIM + d];
        #pragma unroll
        for (int u = 0; u < 16; u++)
            acc = fmaf(t_s[ks*128 + u0 + u], v[u], acc);
    }
    part[ks][d] = acc;
    __syncthreads();
    if (tid < 64)
        qh_s[tid] = part[0][tid] + part[1][tid] + part[2][tid] + part[3][tid] + b2[e*HDIM + tid];
    __syncthreads();

    {
        int ch = tid;
        const float4* wk = (const float4*)(w_kv + (size_t)ch*(2*HS) + e*(2*HDIM));
        float s = 0.f;
        #pragma unroll
        for (int d4 = 0; d4 < HDIM/4; d4++) {
            float4 w = wk[d4];
            s = fmaf(qh_s[d4*4+0], w.x, s);
            s = fmaf(qh_s[d4*4+1], w.y, s);
            s = fmaf(qh_s[d4*4+2], w.z, s);
            s = fmaf(qh_s[d4*4+3], w.w, s);
        }
        g_wqc[(b*NHEADS + e)*HIDDEN + ch] = s * rms_w[ch] * ATTN_SCALE;
    }
}

// ---------------- K2: FULLY FUSED kernel ----------------
// Block = one (b,h) row of 32 pixels, 256 threads (8 warps).
// smem (100352 B):
//   region P (33792 B): swq2 ull[1024] | a2_s ull[1024] | s_s f[2048] | rms f[256] | a_s f[2048]
//        -> overlay during out-GEMM: sW uint[32k][264co] tf32
//   region Q (66560 B): cb_t uint[8e*32ch][40px-stride] tf32 (40960 B, phases B/C)
//        -> overlay after phase C: hst uint[32px][520k] tf32 (66560 B)
__global__ __launch_bounds__(256, 2) void k_attn3(
    const float* __restrict__ c,
    const float* __restrict__ w_out, const float* __restrict__ b_out,
    float* __restrict__ out)
{
    extern __shared__ ull smu[];
    ull*   swq2  = smu;              // [ch][4 head-pairs]
    ull*   a2_s  = smu + 1024;       // [n][4 head-pairs][lane]
    float* fb    = (float*)(smu + 2048);
    float* s_s   = fb;               // dots [e][n][p]
    float* rms_s = fb + 2048;        // [n][p]
    float* a_s   = fb + 2304;        // attn*inv_rms [e][n][p]
    uint32* sW   = (uint32*)smu;                      // overlay: tf32 w_out chunk [32][264]
    uint32* cb_t = (uint32*)((char*)smu + 33792);     // tf32 cbar chunk [e*32+ch][40]
    uint32* hst  = (uint32*)((char*)smu + 33792);     // overlay: tf32 H [32px][520]

    int b = blockIdx.x >> 5;
    int h = blockIdx.x & 31;
    int tid = threadIdx.x;
    int warp = tid >> 5, lane = tid & 31;
    int r4 = lane >> 2, c4 = lane & 3;

    for (int i = tid; i < HIDDEN*4; i += 256) {
        int ch = i >> 2, p = i & 3;
        float lo = g_wqc[b*NHEADS*HIDDEN + (2*p)*HIDDEN + ch];
        float hi = g_wqc[b*NHEADS*HIDDEN + (2*p+1)*HIDDEN + ch];
        swq2[i] = pack2(lo, hi);
    }
    __syncthreads();

    // ---- pass A: sumsq + dots (warp = token n, lane = pixel p), MLP=16 ----
    {
        const float* cp = c + ((size_t)(b*NTOK + warp)*HIDDEN)*PIXB + h*WW + lane;
        float ss = 0.f;
        ull sd2[4] = {0ull, 0ull, 0ull, 0ull};
        #pragma unroll 1
        for (int ch0 = 0; ch0 < HIDDEN; ch0 += 16) {
            float v[16];
            #pragma unroll
            for (int u = 0; u < 16; u++) v[u] = cp[(size_t)(ch0+u)*PIXB];
            #pragma unroll
            for (int u = 0; u < 16; u++) {
                int ch = ch0 + u;
                ss = fmaf(v[u], v[u], ss);
                ull v2 = splat2(v[u]);
                ulonglong2 s01 = *(const ulonglong2*)(swq2 + ch*4);
                ulonglong2 s23 = *(const ulonglong2*)(swq2 + ch*4 + 2);
                ffma2(sd2[0], v2, s01.x);
                ffma2(sd2[1], v2, s01.y);
                ffma2(sd2[2], v2, s23.x);
                ffma2(sd2[3], v2, s23.y);
            }
        }
        rms_s[warp*32 + lane] = rsqrtf(ss*(1.0f/HIDDEN) + EPSV);
        #pragma unroll
        for (int p = 0; p < 4; p++) {
            float lo, hi; unpack2(sd2[p], lo, hi);
            s_s[((2*p)*NTOK + warp)*32 + lane]   = lo;
            s_s[((2*p+1)*NTOK + warp)*32 + lane] = hi;
        }
    }
    __syncthreads();

    // ---- softmax ----
    {
        int e = tid >> 5, p = tid & 31;
        float d[NTOK], m = -1e30f;
        #pragma unroll
        for (int n = 0; n < NTOK; n++) {
            d[n] = s_s[(e*NTOK + n)*32 + p] * rms_s[n*32 + p];
            m = fmaxf(m, d[n]);
        }
        float sum = 0.f;
        #pragma unroll
        for (int n = 0; n < NTOK; n++) { d[n] = expf(d[n] - m); sum += d[n]; }
        float inv = 1.f / sum;
        #pragma unroll
        for (int n = 0; n < NTOK; n++)
            a_s[(e*NTOK + n)*32 + p] = d[n] * inv * rms_s[n*32 + p];
    }
    __syncthreads();

    for (int i = tid; i < 1024; i += 256) {
        int n = i >> 7, p = (i >> 5) & 3, l2 = i & 31;
        float lo = a_s[((2*p)*NTOK + n)*32 + l2];
        float hi = a_s[((2*p+1)*NTOK + n)*32 + l2];
        a2_s[i] = pack2(lo, hi);
    }
    __syncthreads();

    // ---- chunked (32-ch) cbar + per-head V-GEMM via tf32 MMA ----
    // Warp = head e. D[m][n][4]: full 64d x 32px in MMA fragments.
    float D[4][4][4];
    #pragma unroll
    for (int m = 0; m < 4; m++)
        #pragma unroll
        for (int n = 0; n < 4; n++)
            #pragma unroll
            for (int t = 0; t < 4; t++) D[m][n][t] = 0.f;

    for (int cbk = 0; cbk < 8; cbk++) {
        // phase B: cbar chunk (32 ch), warp covers 4 channels, all 8 heads via pairs
        #pragma unroll
        for (int cc = 0; cc < 4; cc++) {
            int chl = warp*4 + cc;               // 0..31
            int ch  = cbk*32 + chl;
            const float* cp = c + ((size_t)(b*NTOK)*HIDDEN + ch)*PIXB + h*WW + lane;
            float v[NTOK];
            #pragma unroll
            for (int n = 0; n < NTOK; n++) v[n] = cp[(size_t)n*HIDDEN*PIXB];
            ull cb2[4] = {0ull, 0ull, 0ull, 0ull};
            #pragma unroll
            for (int n = 0; n < NTOK; n++) {
                ull v2 = splat2(v[n]);
                ffma2(cb2[0], v2, a2_s[(n*4 + 0)*32 + lane]);
                ffma2(cb2[1], v2, a2_s[(n*4 + 1)*32 + lane]);
                ffma2(cb2[2], v2, a2_s[(n*4 + 2)*32 + lane]);
                ffma2(cb2[3], v2, a2_s[(n*4 + 3)*32 + lane]);
            }
            #pragma unroll
            for (int p = 0; p < 4; p++) {
                float lo, hi; unpack2(cb2[p], lo, hi);
                cb_t[((2*p)*32 + chl)*40 + lane]   = cvt_tf32(lo);
                cb_t[((2*p+1)*32 + chl)*40 + lane] = cvt_tf32(hi);
            }
        }
        __syncthreads();

        // phase C: warp = head e; D += Wv_e^T @ cbar_e over this 32-ch chunk (K=32)
        #pragma unroll
        for (int kt = 0; kt < 4; kt++) {
            uint32 bfr[4][2];
            #pragma unroll
            for (int n = 0; n < 4; n++) {
                bfr[n][0] = cb_t[(warp*32 + kt*8 + c4)*40 + n*8 + r4];
                bfr[n][1] = cb_t[(warp*32 + kt*8 + c4 + 4)*40 + n*8 + r4];
            }
            #pragma unroll
            for (int m = 0; m < 4; m++) {
                uint4 af = g_wvt[((warp*32 + cbk*4 + kt)*4 + m)*32 + lane];
                #pragma unroll
                for (int n = 0; n < 4; n++)
                    mma_tf32(D[m][n], (const uint32*)&af, bfr[n]);
            }
        }
        __syncthreads();
    }

    // ---- stage H as tf32 into hst[px][520 + d'] (overlay on cb_t; cb_t is dead) ----
    #pragma unroll
    for (int m = 0; m < 4; m++) {
        int d_lo = warp*HDIM + m*16 + r4;
        #pragma unroll
        for (int n = 0; n < 4; n++) {
            int pxa = n*8 + 2*c4;
            hst[pxa*520 + d_lo]           = cvt_tf32(D[m][n][0]);
            hst[(pxa+1)*520 + d_lo]       = cvt_tf32(D[m][n][1]);
            hst[pxa*520 + d_lo + 8]       = cvt_tf32(D[m][n][2]);
            hst[(pxa+1)*520 + d_lo + 8]   = cvt_tf32(D[m][n][3]);
        }
    }
    __syncthreads();

    // ---- out-GEMM via tf32 mma: out[co 32/warp][32px] = W_out^T @ H + bias ----
    float D2[2][4][4];
    #pragma unroll
    for (int m = 0; m < 2; m++)
        #pragma unroll
        for (int n = 0; n < 4; n++)
            #pragma unroll
            for (int t = 0; t < 4; t++) D2[m][n][t] = 0.f;

    const float4* wf4 = (const float4*)w_out;
    for (int kc = 0; kc < HS; kc += 32) {
        #pragma unroll
        for (int i = 0; i < 8; i++) {
            int f4i = tid + i*256;
            int k = f4i >> 6, co4 = f4i & 63;
            float4 w = wf4[(size_t)(kc + k)*64 + co4];
            uint4 t;
            t.x = cvt_tf32(w.x); t.y = cvt_tf32(w.y);
            t.z = cvt_tf32(w.z); t.w = cvt_tf32(w.w);
            *(uint4*)&sW[k*264 + co4*4] = t;
        }
        __syncthreads();
        #pragma unroll
        for (int kt = 0; kt < 4; kt++) {
            int lk = kt*8;
            uint32 afr[2][4], bfr[4][2];
            #pragma unroll
            for (int m = 0; m < 2; m++) {
                int co = warp*32 + m*16 + r4;
                afr[m][0] = sW[(lk + c4)*264 + co];
                afr[m][1] = sW[(lk + c4)*264 + co + 8];
                afr[m][2] = sW[(lk + c4 + 4)*264 + co];
                afr[m][3] = sW[(lk + c4 + 4)*264 + co + 8];
            }
            #pragma unroll
            for (int n = 0; n < 4; n++) {
                int px = n*8 + r4;
                bfr[n][0] = hst[px*520 + kc + lk + c4];
                bfr[n][1] = hst[px*520 + kc + lk + c4 + 4];
            }
            #pragma unroll
            for (int m = 0; m < 2; m++)
                #pragma unroll
                for (int n = 0; n < 4; n++)
                    mma_tf32(D2[m][n], afr[m], bfr[n]);
        }
        __syncthreads();
    }

    // epilogue
    #pragma unroll
    for (int m = 0; m < 2; m++) {
        int co0 = warp*32 + m*16 + r4;
        float bl = b_out[co0], bh = b_out[co0 + 8];
        #pragma unroll
        for (int n = 0; n < 4; n++) {
            int px = n*8 + 2*c4;
            float* d0 = out + ((size_t)(b*HIDDEN + co0))*PIXB + h*WW + px;
            float* d1 = out + ((size_t)(b*HIDDEN + co0 + 8))*PIXB + h*WW + px;
            *(float2*)d0 = make_float2(D2[m][n][0] + bl, D2[m][n][1] + bl);
            *(float2*)d1 = make_float2(D2[m][n][2] + bh, D2[m][n][3] + bh);
        }
    }
}

// ---------------- launch ----------------
extern "C" void kernel_launch(void* const* d_in, const int* in_sizes, int n_in,
                              void* d_out, int out_size)
{
    const int*   q     = (const int*)  d_in[0];
    const float* c     = (const float*)d_in[1];
    const float* rms_w = (const float*)d_in[2];
    const float* emb   = (const float*)d_in[3];
    const float* w1    = (const float*)d_in[4];
    const float* b1    = (const float*)d_in[5];
    const float* w2    = (const float*)d_in[6];
    const float* b2    = (const float*)d_in[7];
    const float* w_kv  = (const float*)d_in[8];
    const float* w_out = (const float*)d_in[9];
    const float* b_out = (const float*)d_in[10];
    float* out = (float*)d_out;

    const int ATTN_SMEM = 33792 + 66560;   // 100352 B
    cudaFuncSetAttribute(k_attn3, cudaFuncAttributeMaxDynamicSharedMemorySize, ATTN_SMEM);

    k_front<<<128 + 64, 256>>>(w_kv, rms_w, q, emb, w1, b1);
    k_mid  <<<BATCH*NHEADS, 256>>>(w2, b2, w_kv, rms_w);
    k_attn3<<<BATCH*HH, 256, ATTN_SMEM>>>(c, w_out, b_out, out);
}

// round 10
// speedup vs baseline: 4.0863x; 1.2562x over previous
#include <cuda_runtime.h>
#include <cuda_bf16.h>
#include <math.h>

#define HIDDEN 256
#define HS     512
#define NHEADS 8
#define HDIM   64
#define NTOK   8
#define BATCH  8
#define HH     32
#define WW     32
#define PIXB   (HH*WW)        // 1024 pixels per batch
#define NPIX   (BATCH*PIXB)   // 8192
#define EPSV   1e-6f
#define ATTN_SCALE 0.125f     // 64^-0.5

typedef unsigned long long ull;
typedef unsigned int uint32;

// ---- packed f32x2 helpers (FFMA2) ----
__device__ __forceinline__ ull pack2(float lo, float hi) {
    ull r; asm("mov.b64 %0, {%1, %2};" : "=l"(r) : "f"(lo), "f"(hi)); return r;
}
__device__ __forceinline__ ull splat2(float x) {
    ull r; asm("mov.b64 %0, {%1, %1};" : "=l"(r) : "f"(x)); return r;
}
__device__ __forceinline__ void unpack2(ull p, float& lo, float& hi) {
    asm("mov.b64 {%0, %1}, %2;" : "=f"(lo), "=f"(hi) : "l"(p));
}
__device__ __forceinline__ void ffma2(ull& d, ull a, ull b) {
    asm("fma.rn.f32x2 %0, %1, %2, %0;" : "+l"(d) : "l"(a), "l"(b));
}

// ---- tf32 mma helpers ----
__device__ __forceinline__ uint32 cvt_tf32(float x) {
    uint32 r; asm("cvt.rna.tf32.f32 %0, %1;" : "=r"(r) : "f"(x)); return r;
}
__device__ __forceinline__ void mma_tf32(float* d, const uint32* a, const uint32* b) {
    asm volatile("mma.sync.aligned.m16n8k8.row.col.f32.tf32.tf32.f32 "
        "{%0,%1,%2,%3}, {%4,%5,%6,%7}, {%8,%9}, {%0,%1,%2,%3};"
        : "+f"(d[0]), "+f"(d[1]), "+f"(d[2]), "+f"(d[3])
        : "r"(a[0]), "r"(a[1]), "r"(a[2]), "r"(a[3]), "r"(b[0]), "r"(b[1]));
}

// ---------------- device scratch ----------------
__device__ float g_t[BATCH*HS];                  // silu(qe@w1+b1)
__device__ float g_wqc[BATCH*NHEADS*HIDDEN];     // [b][e][256]  (scale & rms_w folded)
// V weights as tf32 MMA A-fragments: [e][kk(32)][m(4)][lane(32)] uint4
__device__ uint4 g_wvt[NHEADS*32*4*32];
// w_out as tf32 MMA A-fragments: [kk(64)][mt(16 co-tiles)][lane(32)] uint4
//   reg0=(co0+r4, k0+c4) reg1=(co0+8+r4, k0+c4) reg2=(co0+r4, k0+c4+4) reg3=(co0+8+r4, k0+c4+4)
__device__ uint4 g_wot[64*16*32];

// ---------------- K0: wv frag (0..127) || w_out frag (128..255) || MLP layer 1 (256..319) ----------------
__global__ __launch_bounds__(256) void k_front(
    const float* __restrict__ w_kv, const float* __restrict__ rms_w,
    const int* __restrict__ q, const float* __restrict__ emb,
    const float* __restrict__ w1, const float* __restrict__ b1,
    const float* __restrict__ w_out)
{
    __shared__ float qe[HIDDEN];
    __shared__ float part[4][64];
    int tid = threadIdx.x;

    if (blockIdx.x < 128) {
        int t = blockIdx.x*256 + tid;        // 0..32767
        int lane = t & 31, m = (t >> 5) & 3, kk = (t >> 7) & 31, e = t >> 12;
        int r4 = lane >> 2, c4 = lane & 3;
        int ch0 = kk*8 + c4, d0 = m*16 + r4;
        const float* base = w_kv + e*(2*HDIM) + HDIM;
        float rw0 = rms_w[ch0], rw4 = rms_w[ch0 + 4];
        uint4 o;
        o.x = cvt_tf32(rw0 * base[(size_t)ch0*(2*HS) + d0]);
        o.y = cvt_tf32(rw0 * base[(size_t)ch0*(2*HS) + d0 + 8]);
        o.z = cvt_tf32(rw4 * base[(size_t)(ch0+4)*(2*HS) + d0]);
        o.w = cvt_tf32(rw4 * base[(size_t)(ch0+4)*(2*HS) + d0 + 8]);
        g_wvt[t] = o;
        return;
    }
    if (blockIdx.x < 256) {
        int t = (blockIdx.x - 128)*256 + tid;   // 0..32767
        int lane = t & 31, mt = (t >> 5) & 15, kk = t >> 9;   // kk 0..63
        int r4 = lane >> 2, c4 = lane & 3;
        int co0 = mt*16, k0 = kk*8;
        uint4 o;
        o.x = cvt_tf32(w_out[(size_t)(k0 + c4)*HIDDEN + co0 + r4]);
        o.y = cvt_tf32(w_out[(size_t)(k0 + c4)*HIDDEN + co0 + 8 + r4]);
        o.z = cvt_tf32(w_out[(size_t)(k0 + c4 + 4)*HIDDEN + co0 + r4]);
        o.w = cvt_tf32(w_out[(size_t)(k0 + c4 + 4)*HIDDEN + co0 + 8 + r4]);
        g_wot[t] = o;
        return;
    }

    int idx = blockIdx.x - 256;          // 0..63
    int b  = idx >> 3;
    int c0 = (idx & 7) * 64;
    qe[tid] = emb[q[b]*HIDDEN + tid];
    __syncthreads();

    int col = tid & 63, ks = tid >> 6;
    float acc = 0.f;
    #pragma unroll 1
    for (int u0 = 0; u0 < 64; u0 += 16) {
        float v[16];
        #pragma unroll
        for (int u = 0; u < 16; u++)
            v[u] = w1[(size_t)(ks*64 + u0 + u)*HS + c0 + col];
        #pragma unroll
        for (int u = 0; u < 16; u++)
            acc = fmaf(qe[ks*64 + u0 + u], v[u], acc);
    }
    part[ks][col] = acc;
    __syncthreads();
    if (tid < 64) {
        float s = part[0][tid] + part[1][tid] + part[2][tid] + part[3][tid] + b1[c0 + tid];
        g_t[b*HS + c0 + tid] = s / (1.f + expf(-s));
    }
}

// ---------------- K1: fused MLP layer 2 + wqc ----------------
__global__ __launch_bounds__(256) void k_mid(
    const float* __restrict__ w2, const float* __restrict__ b2,
    const float* __restrict__ w_kv, const float* __restrict__ rms_w)
{
    __shared__ float t_s[HS];
    __shared__ float part[4][64];
    __shared__ float qh_s[HDIM];
    int tid = threadIdx.x;
    int b = blockIdx.x >> 3, e = blockIdx.x & 7;

    t_s[tid]       = g_t[b*HS + tid];
    t_s[tid + 256] = g_t[b*HS + tid + 256];
    __syncthreads();

    int d = tid & 63, ks = tid >> 6;
    float acc = 0.f;
    #pragma unroll 1
    for (int u0 = 0; u0 < 128; u0 += 16) {
        float v[16];
        #pragma unroll
        for (int u = 0; u < 16; u++)
            v[u] = w2[(size_t)(ks*128 + u0 + u)*HS + e*HDIM + d];
        #pragma unroll
        for (int u = 0; u < 16; u++)
            acc = fmaf(t_s[ks*128 + u0 + u], v[u], acc);
    }
    part[ks][d] = acc;
    __syncthreads();
    if (tid < 64)
        qh_s[tid] = part[0][tid] + part[1][tid] + part[2][tid] + part[3][tid] + b2[e*HDIM + tid];
    __syncthreads();

    {
        int ch = tid;
        const float4* wk = (const float4*)(w_kv + (size_t)ch*(2*HS) + e*(2*HDIM));
        float s = 0.f;
        #pragma unroll
        for (int d4 = 0; d4 < HDIM/4; d4++) {
            float4 w = wk[d4];
            s = fmaf(qh_s[d4*4+0], w.x, s);
            s = fmaf(qh_s[d4*4+1], w.y, s);
            s = fmaf(qh_s[d4*4+2], w.z, s);
            s = fmaf(qh_s[d4*4+3], w.w, s);
        }
        g_wqc[(b*NHEADS + e)*HIDDEN + ch] = s * rms_w[ch] * ATTN_SCALE;
    }
}

// ---------------- K2: FULLY FUSED kernel ----------------
// Block = one (b,h) row of 32 pixels, 256 threads (8 warps).
// smem (100352 B):
//   region P (33792 B): swq2 ull[1024] | a2_s ull[1024] | s_s f[2048] | rms f[256] | a_s f[2048]
//   region Q (66560 B): cb_t uint[8e*32ch][40] tf32 (40960 B, phases B/C)
//        -> overlay after phase C: hst uint[32px][520k] tf32 (66560 B)
__global__ __launch_bounds__(256, 2) void k_attn3(
    const float* __restrict__ c, const float* __restrict__ b_out,
    float* __restrict__ out)
{
    extern __shared__ ull smu[];
    ull*   swq2  = smu;              // [ch][4 head-pairs]
    ull*   a2_s  = smu + 1024;       // [n][4 head-pairs][lane]
    float* fb    = (float*)(smu + 2048);
    float* s_s   = fb;               // dots [e][n][p]
    float* rms_s = fb + 2048;        // [n][p]
    float* a_s   = fb + 2304;        // attn*inv_rms [e][n][p]
    uint32* cb_t = (uint32*)((char*)smu + 33792);     // tf32 cbar chunk [e*32+ch][40]
    uint32* hst  = (uint32*)((char*)smu + 33792);     // overlay: tf32 H [32px][520]

    int b = blockIdx.x >> 5;
    int h = blockIdx.x & 31;
    int tid = threadIdx.x;
    int warp = tid >> 5, lane = tid & 31;
    int r4 = lane >> 2, c4 = lane & 3;

    for (int i = tid; i < HIDDEN*4; i += 256) {
        int ch = i >> 2, p = i & 3;
        float lo = g_wqc[b*NHEADS*HIDDEN + (2*p)*HIDDEN + ch];
        float hi = g_wqc[b*NHEADS*HIDDEN + (2*p+1)*HIDDEN + ch];
        swq2[i] = pack2(lo, hi);
    }
    __syncthreads();

    // ---- pass A: sumsq + dots (warp = token n, lane = pixel p), MLP=16 ----
    {
        const float* cp = c + ((size_t)(b*NTOK + warp)*HIDDEN)*PIXB + h*WW + lane;
        float ss = 0.f;
        ull sd2[4] = {0ull, 0ull, 0ull, 0ull};
        #pragma unroll 1
        for (int ch0 = 0; ch0 < HIDDEN; ch0 += 16) {
            float v[16];
            #pragma unroll
            for (int u = 0; u < 16; u++) v[u] = cp[(size_t)(ch0+u)*PIXB];
            #pragma unroll
            for (int u = 0; u < 16; u++) {
                int ch = ch0 + u;
                ss = fmaf(v[u], v[u], ss);
                ull v2 = splat2(v[u]);
                ulonglong2 s01 = *(const ulonglong2*)(swq2 + ch*4);
                ulonglong2 s23 = *(const ulonglong2*)(swq2 + ch*4 + 2);
                ffma2(sd2[0], v2, s01.x);
                ffma2(sd2[1], v2, s01.y);
                ffma2(sd2[2], v2, s23.x);
                ffma2(sd2[3], v2, s23.y);
            }
        }
        rms_s[warp*32 + lane] = rsqrtf(ss*(1.0f/HIDDEN) + EPSV);
        #pragma unroll
        for (int p = 0; p < 4; p++) {
            float lo, hi; unpack2(sd2[p], lo, hi);
            s_s[((2*p)*NTOK + warp)*32 + lane]   = lo;
            s_s[((2*p+1)*NTOK + warp)*32 + lane] = hi;
        }
    }
    __syncthreads();

    // ---- softmax ----
    {
        int e = tid >> 5, p = tid & 31;
        float d[NTOK], m = -1e30f;
        #pragma unroll
        for (int n = 0; n < NTOK; n++) {
            d[n] = s_s[(e*NTOK + n)*32 + p] * rms_s[n*32 + p];
            m = fmaxf(m, d[n]);
        }
        float sum = 0.f;
        #pragma unroll
        for (int n = 0; n < NTOK; n++) { d[n] = expf(d[n] - m); sum += d[n]; }
        float inv = 1.f / sum;
        #pragma unroll
        for (int n = 0; n < NTOK; n++)
            a_s[(e*NTOK + n)*32 + p] = d[n] * inv * rms_s[n*32 + p];
    }
    __syncthreads();

    for (int i = tid; i < 1024; i += 256) {
        int n = i >> 7, p = (i >> 5) & 3, l2 = i & 31;
        float lo = a_s[((2*p)*NTOK + n)*32 + l2];
        float hi = a_s[((2*p+1)*NTOK + n)*32 + l2];
        a2_s[i] = pack2(lo, hi);
    }
    __syncthreads();

    // ---- chunked (32-ch) cbar + per-head V-GEMM via tf32 MMA ----
    float D[4][4][4];
    #pragma unroll
    for (int m = 0; m < 4; m++)
        #pragma unroll
        for (int n = 0; n < 4; n++)
            #pragma unroll
            for (int t = 0; t < 4; t++) D[m][n][t] = 0.f;

    for (int cbk = 0; cbk < 8; cbk++) {
        // phase B: cbar chunk (32 ch), warp covers 4 channels; 2 channels batched (MLP=16)
        #pragma unroll
        for (int cc = 0; cc < 2; cc++) {
            int chl = warp*4 + cc*2;             // local ch pair base
            int ch  = cbk*32 + chl;
            const float* cp = c + ((size_t)(b*NTOK)*HIDDEN + ch)*PIXB + h*WW + lane;
            float v[2][NTOK];
            #pragma unroll
            for (int n = 0; n < NTOK; n++) {
                v[0][n] = cp[(size_t)n*HIDDEN*PIXB];
                v[1][n] = cp[(size_t)n*HIDDEN*PIXB + PIXB];
            }
            #pragma unroll
            for (int s = 0; s < 2; s++) {
                ull cb2[4] = {0ull, 0ull, 0ull, 0ull};
                #pragma unroll
                for (int n = 0; n < NTOK; n++) {
                    ull v2 = splat2(v[s][n]);
                    ffma2(cb2[0], v2, a2_s[(n*4 + 0)*32 + lane]);
                    ffma2(cb2[1], v2, a2_s[(n*4 + 1)*32 + lane]);
                    ffma2(cb2[2], v2, a2_s[(n*4 + 2)*32 + lane]);
                    ffma2(cb2[3], v2, a2_s[(n*4 + 3)*32 + lane]);
                }
                #pragma unroll
                for (int p = 0; p < 4; p++) {
                    float lo, hi; unpack2(cb2[p], lo, hi);
                    cb_t[((2*p)*32 + chl + s)*40 + lane]   = cvt_tf32(lo);
                    cb_t[((2*p+1)*32 + chl + s)*40 + lane] = cvt_tf32(hi);
                }
            }
        }
        __syncthreads();

        // phase C: warp = head e; D += Wv_e^T @ cbar_e over this 32-ch chunk
        #pragma unroll
        for (int kt = 0; kt < 4; kt++) {
            uint32 bfr[4][2];
            #pragma unroll
            for (int n = 0; n < 4; n++) {
                bfr[n][0] = cb_t[(warp*32 + kt*8 + c4)*40 + n*8 + r4];
                bfr[n][1] = cb_t[(warp*32 + kt*8 + c4 + 4)*40 + n*8 + r4];
            }
            #pragma unroll
            for (int m = 0; m < 4; m++) {
                uint4 af = g_wvt[((warp*32 + cbk*4 + kt)*4 + m)*32 + lane];
                #pragma unroll
                for (int n = 0; n < 4; n++)
                    mma_tf32(D[m][n], (const uint32*)&af, bfr[n]);
            }
        }
        __syncthreads();
    }

    // ---- stage H as tf32 into hst[px][520 + d'] ----
    #pragma unroll
    for (int m = 0; m < 4; m++) {
        int d_lo = warp*HDIM + m*16 + r4;
        #pragma unroll
        for (int n = 0; n < 4; n++) {
            int pxa = n*8 + 2*c4;
            hst[pxa*520 + d_lo]           = cvt_tf32(D[m][n][0]);
            hst[(pxa+1)*520 + d_lo]       = cvt_tf32(D[m][n][1]);
            hst[pxa*520 + d_lo + 8]       = cvt_tf32(D[m][n][2]);
            hst[(pxa+1)*520 + d_lo + 8]   = cvt_tf32(D[m][n][3]);
        }
    }
    __syncthreads();

    // ---- out-GEMM via tf32 mma, A-fragments straight from g_wot (no staging, no syncs) ----
    float D2[2][4][4];
    #pragma unroll
    for (int m = 0; m < 2; m++)
        #pragma unroll
        for (int n = 0; n < 4; n++)
            #pragma unroll
            for (int t = 0; t < 4; t++) D2[m][n][t] = 0.f;

    #pragma unroll 4
    for (int kk = 0; kk < 64; kk++) {
        uint4 af0 = g_wot[(kk*16 + warp*2    )*32 + lane];
        uint4 af1 = g_wot[(kk*16 + warp*2 + 1)*32 + lane];
        uint32 bfr[4][2];
        #pragma unroll
        for (int n = 0; n < 4; n++) {
            bfr[n][0] = hst[(n*8 + r4)*520 + kk*8 + c4];
            bfr[n][1] = hst[(n*8 + r4)*520 + kk*8 + c4 + 4];
        }
        #pragma unroll
        for (int n = 0; n < 4; n++) {
            mma_tf32(D2[0][n], (const uint32*)&af0, bfr[n]);
            mma_tf32(D2[1][n], (const uint32*)&af1, bfr[n]);
        }
    }

    // epilogue
    #pragma unroll
    for (int m = 0; m < 2; m++) {
        int co0 = warp*32 + m*16 + r4;
        float bl = b_out[co0], bh = b_out[co0 + 8];
        #pragma unroll
        for (int n = 0; n < 4; n++) {
            int px = n*8 + 2*c4;
            float* d0 = out + ((size_t)(b*HIDDEN + co0))*PIXB + h*WW + px;
            float* d1 = out + ((size_t)(b*HIDDEN + co0 + 8))*PIXB + h*WW + px;
            *(float2*)d0 = make_float2(D2[m][n][0] + bl, D2[m][n][1] + bl);
            *(float2*)d1 = make_float2(D2[m][n][2] + bh, D2[m][n][3] + bh);
        }
    }
}

// ---------------- launch ----------------
extern "C" void kernel_launch(void* const* d_in, const int* in_sizes, int n_in,
                              void* d_out, int out_size)
{
    const int*   q     = (const int*)  d_in[0];
    const float* c     = (const float*)d_in[1];
    const float* rms_w = (const float*)d_in[2];
    const float* emb   = (const float*)d_in[3];
    const float* w1    = (const float*)d_in[4];
    const float* b1    = (const float*)d_in[5];
    const float* w2    = (const float*)d_in[6];
    const float* b2    = (const float*)d_in[7];
    const float* w_kv  = (const float*)d_in[8];
    const float* w_out = (const float*)d_in[9];
    const float* b_out = (const float*)d_in[10];
    float* out = (float*)d_out;

    const int ATTN_SMEM = 33792 + 66560;   // 100352 B
    cudaFuncSetAttribute(k_attn3, cudaFuncAttributeMaxDynamicSharedMemorySize, ATTN_SMEM);

    k_front<<<256 + 64, 256>>>(w_kv, rms_w, q, emb, w1, b1, w_out);
    k_mid  <<<BATCH*NHEADS, 256>>>(w2, b2, w_kv, rms_w);
    k_attn3<<<BATCH*HH, 256, ATTN_SMEM>>>(c, b_out, out);
}